// round 1
// baseline (speedup 1.0000x reference)
#include <cuda_runtime.h>
#include <cuda_bf16.h>
#include <math.h>

// Problem constants
#define Bn   4
#define Tn   2048
#define Cn   1024
#define Hn   16
#define HSn  64
#define DFFn 4096
#define Mn   (Bn*Tn)          // 8192 rows

// ---------------- scratch (allocation-free: __device__ globals) -------------
__device__ float g_buf0[Mn*Cn];   // ln1 -> (reused) attn-out y -> (reused) ln2 out
__device__ float g_q  [Mn*Cn];
__device__ float g_k  [Mn*Cn];
__device__ float g_v  [Mn*Cn];
__device__ float g_x2 [Mn*Cn];    // x + attn (residual stream)
__device__ float g_ff [Mn*DFFn];  // relu(h@W1+b1)

// ---------------- LayerNorm: one block (256 thr) per row of 1024 ------------
__global__ void ln_kernel(const float* __restrict__ x, const float* __restrict__ g,
                          const float* __restrict__ be, float* __restrict__ out) {
    __shared__ float sh1[8];
    __shared__ float sh2[8];
    const int row = blockIdx.x;
    const int t = threadIdx.x;                  // 256 threads, 4 elems each
    const float4* xr = (const float4*)(x + (size_t)row * Cn);
    float4 v = xr[t];

    float s = v.x + v.y + v.z + v.w;
    #pragma unroll
    for (int off = 16; off; off >>= 1) s += __shfl_down_sync(0xffffffffu, s, off);
    if ((t & 31) == 0) sh1[t >> 5] = s;
    __syncthreads();
    float tot = sh1[0]+sh1[1]+sh1[2]+sh1[3]+sh1[4]+sh1[5]+sh1[6]+sh1[7];
    float mu = tot * (1.0f / Cn);

    float dx = v.x - mu, dy = v.y - mu, dz = v.z - mu, dw = v.w - mu;
    float ss = dx*dx + dy*dy + dz*dz + dw*dw;
    #pragma unroll
    for (int off = 16; off; off >>= 1) ss += __shfl_down_sync(0xffffffffu, ss, off);
    if ((t & 31) == 0) sh2[t >> 5] = ss;
    __syncthreads();
    float var = (sh2[0]+sh2[1]+sh2[2]+sh2[3]+sh2[4]+sh2[5]+sh2[6]+sh2[7]) * (1.0f / Cn);
    float rstd = rsqrtf(var + 1e-5f);

    float4 gg = ((const float4*)g)[t];
    float4 bb = ((const float4*)be)[t];
    float4 r;
    r.x = dx * rstd * gg.x + bb.x;
    r.y = dy * rstd * gg.y + bb.y;
    r.z = dz * rstd * gg.z + bb.z;
    r.w = dw * rstd * gg.w + bb.w;
    ((float4*)(out + (size_t)row * Cn))[t] = r;
}

// ---------------- SGEMM: C = A[M,K] @ W[K,N] + bias (+relu / +residual) -----
// Tiles: 128x64x16, 256 threads, 8x4 per-thread microtile. All dims divide.
#define GBM 128
#define GBN 64
#define GBK 16

template<bool RELU, bool RES>
__global__ __launch_bounds__(256) void gemm_kernel(
        const float* __restrict__ A, const float* __restrict__ W,
        const float* __restrict__ bias, const float* __restrict__ res,
        float* __restrict__ Cout, int M, int N, int K) {
    __shared__ float As[GBK][GBM + 4];   // transposed A tile (pad vs bank conflicts)
    __shared__ float Bs[GBK][GBN + 4];

    const int bn = blockIdx.x * GBN;
    const int bm = blockIdx.y * GBM;
    const int tid = threadIdx.x;
    const int tx = tid & 15;             // 16 col-groups * 4 cols
    const int ty = tid >> 4;             // 16 row-groups * 8 rows

    float acc[8][4];
    #pragma unroll
    for (int i = 0; i < 8; i++)
        #pragma unroll
        for (int j = 0; j < 4; j++) acc[i][j] = 0.0f;

    for (int k0 = 0; k0 < K; k0 += GBK) {
        // A tile: 128x16 floats = 512 float4, 2 per thread (store transposed)
        #pragma unroll
        for (int i = 0; i < 2; i++) {
            int slot = tid + i * 256;            // 0..511
            int r  = slot >> 2;                  // 0..127
            int kv = (slot & 3) << 2;            // 0,4,8,12
            float4 a = *(const float4*)(A + (size_t)(bm + r) * K + k0 + kv);
            As[kv + 0][r] = a.x; As[kv + 1][r] = a.y;
            As[kv + 2][r] = a.z; As[kv + 3][r] = a.w;
        }
        // B tile: 16x64 floats = 256 float4, 1 per thread
        {
            int r  = tid >> 4;                   // 0..15
            int cv = (tid & 15) << 2;            // 0..60
            *(float4*)&Bs[r][cv] = *(const float4*)(W + (size_t)(k0 + r) * N + bn + cv);
        }
        __syncthreads();
        #pragma unroll
        for (int kk = 0; kk < GBK; kk++) {
            float a[8], b[4];
            *(float4*)&a[0] = *(const float4*)&As[kk][ty * 8];
            *(float4*)&a[4] = *(const float4*)&As[kk][ty * 8 + 4];
            *(float4*)&b[0] = *(const float4*)&Bs[kk][tx * 4];
            #pragma unroll
            for (int i = 0; i < 8; i++)
                #pragma unroll
                for (int j = 0; j < 4; j++)
                    acc[i][j] = fmaf(a[i], b[j], acc[i][j]);
        }
        __syncthreads();
    }

    #pragma unroll
    for (int i = 0; i < 8; i++) {
        int row = bm + ty * 8 + i;
        #pragma unroll
        for (int j = 0; j < 4; j++) {
            int col = bn + tx * 4 + j;
            float v = acc[i][j] + bias[col];
            if (RELU) v = fmaxf(v, 0.0f);
            if (RES)  v += res[(size_t)row * N + col];
            Cout[(size_t)row * N + col] = v;
        }
    }
}

// ---------------- Fused causal attention (flash-style, fp32) ----------------
// Grid: (T/64, B*H). Block: 64 threads, one query row per thread.
// K/V tiles (64x64) staged in smem; online softmax with rare-rescale branch.
__global__ __launch_bounds__(64) void attn_kernel(
        const float* __restrict__ Q, const float* __restrict__ Kg,
        const float* __restrict__ Vg, float* __restrict__ Y) {
    __shared__ float Ks[64][68];
    __shared__ float Vs[64][68];
    const int qt = blockIdx.x;
    const int bh = blockIdx.y;
    const int b = bh >> 4, h = bh & 15;
    const int ql = threadIdx.x;                  // 0..63
    const int qi = qt * 64 + ql;

    const float* qrow = Q + ((size_t)(b * Tn + qi)) * Cn + h * HSn;
    float qreg[HSn];
    #pragma unroll
    for (int d = 0; d < HSn; d += 4) {
        float4 qv = *(const float4*)(qrow + d);
        qreg[d+0] = qv.x * 0.125f;               // 1/sqrt(64) folded in
        qreg[d+1] = qv.y * 0.125f;
        qreg[d+2] = qv.z * 0.125f;
        qreg[d+3] = qv.w * 0.125f;
    }

    float m = -1e30f, l = 0.0f;
    float o[HSn];
    #pragma unroll
    for (int d = 0; d < HSn; d++) o[d] = 0.0f;

    for (int kt = 0; kt <= qt; kt++) {
        // cooperative coalesced load of K,V tiles: 1024 float4 each
        #pragma unroll
        for (int i = 0; i < 16; i++) {
            int fid = threadIdx.x + i * 64;      // 0..1023
            int r  = fid >> 4;                   // 0..63
            int dv = (fid & 15) << 2;            // 0..60
            size_t gidx = ((size_t)(b * Tn + kt * 64 + r)) * Cn + h * HSn + dv;
            *(float4*)&Ks[r][dv] = *(const float4*)(Kg + gidx);
            *(float4*)&Vs[r][dv] = *(const float4*)(Vg + gidx);
        }
        __syncthreads();

        const int kend = (kt == qt) ? (ql + 1) : 64;
        for (int kj = 0; kj < kend; kj++) {
            float s0 = 0.f, s1 = 0.f, s2 = 0.f, s3 = 0.f;   // break FMA dep chain
            #pragma unroll
            for (int d = 0; d < HSn; d += 4) {
                s0 = fmaf(qreg[d+0], Ks[kj][d+0], s0);
                s1 = fmaf(qreg[d+1], Ks[kj][d+1], s1);
                s2 = fmaf(qreg[d+2], Ks[kj][d+2], s2);
                s3 = fmaf(qreg[d+3], Ks[kj][d+3], s3);
            }
            float s = (s0 + s1) + (s2 + s3);
            if (s <= m) {                        // common path: no rescale
                float p = __expf(s - m);
                l += p;
                #pragma unroll
                for (int d = 0; d < HSn; d++) o[d] = fmaf(p, Vs[kj][d], o[d]);
            } else {                             // rare: new max, rescale
                float corr = __expf(m - s);
                m = s;
                l = fmaf(l, corr, 1.0f);
                #pragma unroll
                for (int d = 0; d < HSn; d++) o[d] = fmaf(o[d], corr, Vs[kj][d]);
            }
        }
        __syncthreads();
    }

    float inv = 1.0f / l;
    float* yrow = Y + ((size_t)(b * Tn + qi)) * Cn + h * HSn;
    #pragma unroll
    for (int d = 0; d < HSn; d += 4) {
        float4 ov;
        ov.x = o[d+0] * inv; ov.y = o[d+1] * inv;
        ov.z = o[d+2] * inv; ov.w = o[d+3] * inv;
        *(float4*)(yrow + d) = ov;
    }
}

// ---------------- launch ----------------------------------------------------
extern "C" void kernel_launch(void* const* d_in, const int* in_sizes, int n_in,
                              void* d_out, int out_size) {
    const float* x   = (const float*)d_in[0];
    const float* Wq  = (const float*)d_in[1];
    const float* bq  = (const float*)d_in[2];
    const float* Wk  = (const float*)d_in[3];
    const float* bk  = (const float*)d_in[4];
    const float* Wv  = (const float*)d_in[5];
    const float* bv  = (const float*)d_in[6];
    const float* Wo  = (const float*)d_in[7];
    const float* bo  = (const float*)d_in[8];
    const float* W1  = (const float*)d_in[9];
    const float* b1  = (const float*)d_in[10];
    const float* W2  = (const float*)d_in[11];
    const float* b2  = (const float*)d_in[12];
    const float* g1  = (const float*)d_in[13];
    const float* be1 = (const float*)d_in[14];
    const float* g2  = (const float*)d_in[15];
    const float* be2 = (const float*)d_in[16];
    float* out = (float*)d_out;

    float *buf0, *q, *k, *v, *x2, *ff;
    cudaGetSymbolAddress((void**)&buf0, g_buf0);
    cudaGetSymbolAddress((void**)&q,    g_q);
    cudaGetSymbolAddress((void**)&k,    g_k);
    cudaGetSymbolAddress((void**)&v,    g_v);
    cudaGetSymbolAddress((void**)&x2,   g_x2);
    cudaGetSymbolAddress((void**)&ff,   g_ff);

    // 1) ln1 = LN(x)
    ln_kernel<<<Mn, 256>>>(x, g1, be1, buf0);

    // 2-4) q,k,v = ln1 @ W{q,k,v} + b   ([BT, C] layout; head = col/64)
    dim3 gQKV(Cn / GBN, Mn / GBM);
    gemm_kernel<false, false><<<gQKV, 256>>>(buf0, Wq, bq, nullptr, q,  Mn, Cn, Cn);
    gemm_kernel<false, false><<<gQKV, 256>>>(buf0, Wk, bk, nullptr, k,  Mn, Cn, Cn);
    gemm_kernel<false, false><<<gQKV, 256>>>(buf0, Wv, bv, nullptr, v,  Mn, Cn, Cn);

    // 5) y = causal_softmax(q k^T / 8) v    (writes [BT, C], reuses buf0)
    attn_kernel<<<dim3(Tn / 64, Bn * Hn), 64>>>(q, k, v, buf0);

    // 6) x2 = x + y @ Wo + bo
    gemm_kernel<false, true><<<gQKV, 256>>>(buf0, Wo, bo, x, x2, Mn, Cn, Cn);

    // 7) h2 = LN(x2)   (reuses buf0)
    ln_kernel<<<Mn, 256>>>(x2, g2, be2, buf0);

    // 8) ff = relu(h2 @ W1 + b1)
    gemm_kernel<true, false><<<dim3(DFFn / GBN, Mn / GBM), 256>>>(
        buf0, W1, b1, nullptr, ff, Mn, DFFn, Cn);

    // 9) out = x2 + ff @ W2 + b2
    gemm_kernel<false, true><<<gQKV, 256>>>(ff, W2, b2, x2, out, Mn, Cn, DFFn);
}

// round 3
// speedup vs baseline: 1.8999x; 1.8999x over previous
#include <cuda_runtime.h>
#include <cstdint>
#include <math.h>

// ---------------- problem constants ----------------
#define Bn   4
#define Tn   2048
#define Cn   1024
#define Hn   16
#define HSn  64
#define DFFn 4096
#define Mn   (Bn*Tn)          // 8192

// ---------------- scratch (__device__ globals; allocation-free) ------------
__device__ float g_buf0[Mn*Cn];                 // ln1 / attn-y / ln2
__device__ float g_qkv [(size_t)Mn*3*Cn];       // merged q|k|v  [M, 3072]
__device__ float g_x2  [Mn*Cn];                 // x + attn
__device__ float g_ff  [(size_t)Mn*DFFn];       // relu(h@W1+b1)
__device__ float g_wtqkv[(size_t)3*Cn*Cn];      // [3072,1024] = (Wq|Wk|Wv)^T
__device__ float g_wto [Cn*Cn];                 // Wo^T  [1024,1024]
__device__ float g_wt1 [(size_t)DFFn*Cn];       // W1^T  [4096,1024]
__device__ float g_wt2 [(size_t)Cn*DFFn];       // W2^T  [1024,4096]
__device__ float g_bqkv[3*Cn];

// ---------------- helpers ----------------
__device__ __forceinline__ uint32_t smem_u32(const void* p) {
    uint32_t a;
    asm("{ .reg .u64 t; cvta.to.shared.u64 t, %1; cvt.u32.u64 %0, t; }" : "=r"(a) : "l"(p));
    return a;
}
__device__ __forceinline__ float rtf32(float x) {
    float r; asm("cvt.rna.tf32.f32 %0, %1;" : "=f"(r) : "f"(x)); return r;
}
__device__ __forceinline__ unsigned long long pk2(float lo, float hi) {
    unsigned long long r; asm("mov.b64 %0, {%1,%2};" : "=l"(r) : "f"(lo), "f"(hi)); return r;
}
__device__ __forceinline__ void upk2(unsigned long long v, float& lo, float& hi) {
    asm("mov.b64 {%0,%1}, %2;" : "=f"(lo), "=f"(hi) : "l"(v));
}
__device__ __forceinline__ unsigned long long fma2(unsigned long long a,
                                                   unsigned long long b,
                                                   unsigned long long c) {
    unsigned long long d;
    asm("fma.rn.f32x2 %0, %1, %2, %3;" : "=l"(d) : "l"(a), "l"(b), "l"(c));
    return d;
}

#define CP16(dst, src) \
    asm volatile("cp.async.cg.shared.global [%0], [%1], 16;" :: "r"(dst), "l"(src))
#define CPCOMMIT() asm volatile("cp.async.commit_group;")
#define CPWAIT1()  asm volatile("cp.async.wait_group 1;" ::: "memory")

// mma.sync m16n8k8 tf32 (sm_80 baseline — assembles at compute_103)
__device__ __forceinline__ void mma8(float* d, const uint32_t* a, const uint32_t* b) {
    asm volatile("mma.sync.aligned.m16n8k8.row.col.f32.tf32.tf32.f32 "
        "{%0,%1,%2,%3}, {%4,%5,%6,%7}, {%8,%9}, {%0,%1,%2,%3};"
        : "+f"(d[0]), "+f"(d[1]), "+f"(d[2]), "+f"(d[3])
        : "r"(a[0]), "r"(a[1]), "r"(a[2]), "r"(a[3]), "r"(b[0]), "r"(b[1]));
}

// ---------------- LayerNorm (outputs tf32-rounded) ----------------
__global__ void ln_kernel(const float* __restrict__ x, const float* __restrict__ g,
                          const float* __restrict__ be, float* __restrict__ out) {
    __shared__ float sh1[8], sh2[8];
    const int row = blockIdx.x;
    const int t = threadIdx.x;
    float4 v = ((const float4*)(x + (size_t)row * Cn))[t];

    float s = v.x + v.y + v.z + v.w;
    #pragma unroll
    for (int o = 16; o; o >>= 1) s += __shfl_down_sync(0xffffffffu, s, o);
    if ((t & 31) == 0) sh1[t >> 5] = s;
    __syncthreads();
    float mu = (sh1[0]+sh1[1]+sh1[2]+sh1[3]+sh1[4]+sh1[5]+sh1[6]+sh1[7]) * (1.0f/Cn);

    float dx = v.x-mu, dy = v.y-mu, dz = v.z-mu, dw = v.w-mu;
    float ss = dx*dx + dy*dy + dz*dz + dw*dw;
    #pragma unroll
    for (int o = 16; o; o >>= 1) ss += __shfl_down_sync(0xffffffffu, ss, o);
    if ((t & 31) == 0) sh2[t >> 5] = ss;
    __syncthreads();
    float rstd = rsqrtf((sh2[0]+sh2[1]+sh2[2]+sh2[3]+sh2[4]+sh2[5]+sh2[6]+sh2[7])*(1.0f/Cn) + 1e-5f);

    float4 gg = ((const float4*)g)[t];
    float4 bb = ((const float4*)be)[t];
    float4 r;
    r.x = rtf32(dx*rstd*gg.x + bb.x);
    r.y = rtf32(dy*rstd*gg.y + bb.y);
    r.z = rtf32(dz*rstd*gg.z + bb.z);
    r.w = rtf32(dw*rstd*gg.w + bb.w);
    ((float4*)(out + (size_t)row * Cn))[t] = r;
}

// ---------------- transpose W[K,N] -> Wt[N,K] (tf32-rounded) ---------------
__global__ void transpose_tf32(const float* __restrict__ W, float* __restrict__ Wt,
                               int K, int N) {
    __shared__ float t[32][33];
    int n0 = blockIdx.x * 32, k0 = blockIdx.y * 32;
    int tx = threadIdx.x, ty = threadIdx.y;     // 32 x 8
    #pragma unroll
    for (int i = 0; i < 32; i += 8)
        t[ty + i][tx] = W[(size_t)(k0 + ty + i) * N + n0 + tx];
    __syncthreads();
    #pragma unroll
    for (int i = 0; i < 32; i += 8)
        Wt[(size_t)(n0 + ty + i) * K + k0 + tx] = rtf32(t[tx][ty + i]);
}

__global__ void concat3(const float* a, const float* b, const float* c, float* o) {
    int t = blockIdx.x * 256 + threadIdx.x;     // 3072
    o[t] = (t < 1024) ? a[t] : ((t < 2048) ? b[t - 1024] : c[t - 2048]);
}

// ---------------- tf32 mma.sync GEMM: C = A[M,K] @ Bt[N,K]^T + bias --------
// block tile 128x128x32, 256 thr = 8 warps (2m x 4n), warp tile 64x32.
// 3-stage cp.async pipeline; smem rows padded to 36 floats (conflict-free).
#define GBM 128
#define GBN 128
#define GBK 32
#define APAD 36
#define STG (GBM*APAD + GBN*APAD)        // floats per stage (9216)
#define GSMEM (3*STG*4)                  // 110592 bytes

template<bool RELU, bool RES, bool RND>
__global__ __launch_bounds__(256, 1) void gemm_mma(
        const float* __restrict__ A, const float* __restrict__ Bt,
        const float* __restrict__ bias, const float* __restrict__ res,
        float* __restrict__ Cout, int M, int N, int K) {
    extern __shared__ float smf[];
    const int tid = threadIdx.x;
    const int lane = tid & 31;
    const int wid = tid >> 5;
    const int g = lane >> 2, t4 = lane & 3;
    const int wm = wid >> 2, wn = wid & 3;       // 2 x 4 warps
    const int bm = blockIdx.y * GBM;
    const int bn = blockIdx.x * GBN;

    float acc[4][4][4];
    #pragma unroll
    for (int i = 0; i < 4; i++)
        #pragma unroll
        for (int j = 0; j < 4; j++)
            #pragma unroll
            for (int p = 0; p < 4; p++) acc[i][j][p] = 0.0f;

    const uint32_t sm0 = smem_u32(smf);

    auto load_chunk = [&](int c, int s) {
        const uint32_t sA = sm0 + s * (STG * 4);
        const uint32_t sB = sA + GBM * APAD * 4;
        const int kc = c * GBK;
        const int r = tid >> 3, cv = tid & 7;    // 32 rows x 8 float4 per pass
        #pragma unroll
        for (int j = 0; j < 4; j++)
            CP16(sA + (r + j*32) * (APAD*4) + cv*16,
                 A + (size_t)(bm + r + j*32) * K + kc + cv*4);
        #pragma unroll
        for (int j = 0; j < 4; j++)
            CP16(sB + (r + j*32) * (APAD*4) + cv*16,
                 Bt + (size_t)(bn + r + j*32) * K + kc + cv*4);
    };

    load_chunk(0, 0); CPCOMMIT();
    load_chunk(1, 1); CPCOMMIT();

    const int nc = K / GBK;
    for (int c = 0; c < nc; c++) {
        CPWAIT1();
        __syncthreads();
        if (c + 2 < nc) load_chunk(c + 2, (c + 2) % 3);
        CPCOMMIT();

        const uint32_t* As = (const uint32_t*)(smf + (c % 3) * STG);
        const uint32_t* Bs = As + GBM * APAD;
        #pragma unroll
        for (int kk = 0; kk < 4; kk++) {
            const int kb = kk * 8;
            uint32_t a[4][4], b[4][2];
            #pragma unroll
            for (int im = 0; im < 4; im++) {
                int r0 = wm*64 + im*16 + g;
                a[im][0] = As[r0*APAD + kb + t4];
                a[im][1] = As[(r0+8)*APAD + kb + t4];
                a[im][2] = As[r0*APAD + kb + t4 + 4];
                a[im][3] = As[(r0+8)*APAD + kb + t4 + 4];
            }
            #pragma unroll
            for (int in = 0; in < 4; in++) {
                int n0 = wn*32 + in*8 + g;
                b[in][0] = Bs[n0*APAD + kb + t4];
                b[in][1] = Bs[n0*APAD + kb + t4 + 4];
            }
            #pragma unroll
            for (int im = 0; im < 4; im++)
                #pragma unroll
                for (int in = 0; in < 4; in++)
                    mma8(acc[im][in], a[im], b[in]);
        }
        __syncthreads();
    }

    // ---- epilogue: frags -> global (bias / relu / rnd / residual)
    #pragma unroll
    for (int im = 0; im < 4; im++) {
        #pragma unroll
        for (int in = 0; in < 4; in++) {
            const float* av = acc[im][in];
            int r0 = bm + wm*64 + im*16 + g;
            int c0 = bn + wn*32 + in*8 + t4*2;
            float b0 = bias[c0], b1 = bias[c0 + 1];
            #pragma unroll
            for (int h = 0; h < 2; h++) {
                int row = r0 + h * 8;
                float v0 = av[h*2 + 0] + b0;
                float v1 = av[h*2 + 1] + b1;
                if (RELU) { v0 = fmaxf(v0, 0.f); v1 = fmaxf(v1, 0.f); }
                if (RND)  { v0 = rtf32(v0); v1 = rtf32(v1); }
                if (RES) {
                    const float2 rr = *(const float2*)(res + (size_t)row * N + c0);
                    v0 += rr.x; v1 += rr.y;
                }
                *(float2*)(Cout + (size_t)row * N + c0) = make_float2(v0, v1);
            }
        }
    }
}

// ---------------- fused causal attention (f32x2 packed math) ---------------
__global__ __launch_bounds__(64) void attn_kernel(
        const float* __restrict__ Q, const float* __restrict__ Kg,
        const float* __restrict__ Vg, float* __restrict__ Y, int ldq) {
    __shared__ float Ks[64][68];
    __shared__ float Vs[64][68];
    const int qt = blockIdx.x;
    const int bh = blockIdx.y;
    const int b = bh >> 4, h = bh & 15;
    const int ql = threadIdx.x;
    const int qi = qt * 64 + ql;

    const float* qrow = Q + (size_t)(b * Tn + qi) * ldq + h * HSn;
    unsigned long long q2[32];
    #pragma unroll
    for (int d = 0; d < HSn; d += 4) {
        float4 qv = *(const float4*)(qrow + d);
        q2[d/2]   = pk2(qv.x * 0.125f, qv.y * 0.125f);
        q2[d/2+1] = pk2(qv.z * 0.125f, qv.w * 0.125f);
    }

    float m = -1e30f, l = 0.0f;
    unsigned long long o2[32];
    #pragma unroll
    for (int d = 0; d < 32; d++) o2[d] = 0ull;

    for (int kt = 0; kt <= qt; kt++) {
        #pragma unroll
        for (int i = 0; i < 16; i++) {
            int fid = threadIdx.x + i * 64;
            int r = fid >> 4, dv = (fid & 15) << 2;
            size_t gidx = (size_t)(b * Tn + kt * 64 + r) * ldq + h * HSn + dv;
            *(float4*)&Ks[r][dv] = *(const float4*)(Kg + gidx);
            *(float4*)&Vs[r][dv] = *(const float4*)(Vg + gidx);
        }
        __syncthreads();

        const int kend = (kt == qt) ? (ql + 1) : 64;
        for (int kj = 0; kj < kend; kj++) {
            const unsigned long long* k2 = (const unsigned long long*)&Ks[kj][0];
            unsigned long long sa = 0, sb = 0, sc = 0, sd = 0;
            #pragma unroll
            for (int d = 0; d < 32; d += 4) {
                sa = fma2(q2[d+0], k2[d+0], sa);
                sb = fma2(q2[d+1], k2[d+1], sb);
                sc = fma2(q2[d+2], k2[d+2], sc);
                sd = fma2(q2[d+3], k2[d+3], sd);
            }
            float a0,a1,b0,b1,c0,c1,d0,d1;
            upk2(sa,a0,a1); upk2(sb,b0,b1); upk2(sc,c0,c1); upk2(sd,d0,d1);
            float s = ((a0+a1)+(b0+b1)) + ((c0+c1)+(d0+d1));

            const unsigned long long* v2 = (const unsigned long long*)&Vs[kj][0];
            if (s <= m) {
                float p = __expf(s - m);
                l += p;
                unsigned long long p2 = pk2(p, p);
                #pragma unroll
                for (int d = 0; d < 32; d++) o2[d] = fma2(p2, v2[d], o2[d]);
            } else {
                float corr = __expf(m - s);
                m = s;
                l = fmaf(l, corr, 1.0f);
                unsigned long long c2 = pk2(corr, corr);
                #pragma unroll
                for (int d = 0; d < 32; d++) o2[d] = fma2(c2, o2[d], v2[d]);
            }
        }
        __syncthreads();
    }

    float inv = 1.0f / l;
    float* yrow = Y + (size_t)(b * Tn + qi) * Cn + h * HSn;
    #pragma unroll
    for (int d = 0; d < 32; d += 2) {
        float x0,x1,x2,x3;
        upk2(o2[d], x0, x1); upk2(o2[d+1], x2, x3);
        float4 ov;
        ov.x = rtf32(x0*inv); ov.y = rtf32(x1*inv);
        ov.z = rtf32(x2*inv); ov.w = rtf32(x3*inv);
        *(float4*)(yrow + d*2) = ov;
    }
}

// ---------------- launch ----------------------------------------------------
extern "C" void kernel_launch(void* const* d_in, const int* in_sizes, int n_in,
                              void* d_out, int out_size) {
    const float* x   = (const float*)d_in[0];
    const float* Wq  = (const float*)d_in[1];
    const float* bq  = (const float*)d_in[2];
    const float* Wk  = (const float*)d_in[3];
    const float* bk  = (const float*)d_in[4];
    const float* Wv  = (const float*)d_in[5];
    const float* bv  = (const float*)d_in[6];
    const float* Wo  = (const float*)d_in[7];
    const float* bo  = (const float*)d_in[8];
    const float* W1  = (const float*)d_in[9];
    const float* b1  = (const float*)d_in[10];
    const float* W2  = (const float*)d_in[11];
    const float* b2  = (const float*)d_in[12];
    const float* g1  = (const float*)d_in[13];
    const float* be1 = (const float*)d_in[14];
    const float* g2  = (const float*)d_in[15];
    const float* be2 = (const float*)d_in[16];
    float* out = (float*)d_out;

    float *buf0, *qkv, *x2, *ff, *wtqkv, *wto, *wt1, *wt2, *bqkv;
    cudaGetSymbolAddress((void**)&buf0,  g_buf0);
    cudaGetSymbolAddress((void**)&qkv,   g_qkv);
    cudaGetSymbolAddress((void**)&x2,    g_x2);
    cudaGetSymbolAddress((void**)&ff,    g_ff);
    cudaGetSymbolAddress((void**)&wtqkv, g_wtqkv);
    cudaGetSymbolAddress((void**)&wto,   g_wto);
    cudaGetSymbolAddress((void**)&wt1,   g_wt1);
    cudaGetSymbolAddress((void**)&wt2,   g_wt2);
    cudaGetSymbolAddress((void**)&bqkv,  g_bqkv);

    cudaFuncSetAttribute(gemm_mma<false,false,false>, cudaFuncAttributeMaxDynamicSharedMemorySize, GSMEM);
    cudaFuncSetAttribute(gemm_mma<false,true ,false>, cudaFuncAttributeMaxDynamicSharedMemorySize, GSMEM);
    cudaFuncSetAttribute(gemm_mma<true ,false,true >, cudaFuncAttributeMaxDynamicSharedMemorySize, GSMEM);

    // weight transposes (tf32-rounded)
    dim3 tb(32, 8);
    transpose_tf32<<<dim3(Cn/32,  Cn/32),  tb>>>(Wq, wtqkv,             Cn,   Cn);
    transpose_tf32<<<dim3(Cn/32,  Cn/32),  tb>>>(Wk, wtqkv + Cn*Cn,     Cn,   Cn);
    transpose_tf32<<<dim3(Cn/32,  Cn/32),  tb>>>(Wv, wtqkv + 2*Cn*Cn,   Cn,   Cn);
    transpose_tf32<<<dim3(Cn/32,  Cn/32),  tb>>>(Wo, wto,               Cn,   Cn);
    transpose_tf32<<<dim3(DFFn/32,Cn/32),  tb>>>(W1, wt1,               Cn,   DFFn);
    transpose_tf32<<<dim3(Cn/32,  DFFn/32),tb>>>(W2, wt2,               DFFn, Cn);
    concat3<<<12, 256>>>(bq, bk, bv, bqkv);

    // 1) ln1
    ln_kernel<<<Mn, 256>>>(x, g1, be1, buf0);

    // 2) merged qkv = ln1 @ [Wq|Wk|Wv] + b   -> [M, 3072]
    gemm_mma<false,false,false><<<dim3(3*Cn/GBN, Mn/GBM), 256, GSMEM>>>(
        buf0, wtqkv, bqkv, nullptr, qkv, Mn, 3*Cn, Cn);

    // 3) attention -> buf0
    attn_kernel<<<dim3(Tn/64, Bn*Hn), 64>>>(qkv, qkv + Cn, qkv + 2*Cn, buf0, 3*Cn);

    // 4) x2 = x + y @ Wo + bo
    gemm_mma<false,true,false><<<dim3(Cn/GBN, Mn/GBM), 256, GSMEM>>>(
        buf0, wto, bo, x, x2, Mn, Cn, Cn);

    // 5) ln2 -> buf0
    ln_kernel<<<Mn, 256>>>(x2, g2, be2, buf0);

    // 6) ff = relu(h @ W1 + b1)  (tf32-rounded)
    gemm_mma<true,false,true><<<dim3(DFFn/GBN, Mn/GBM), 256, GSMEM>>>(
        buf0, wt1, b1, nullptr, ff, Mn, DFFn, Cn);

    // 7) out = x2 + ff @ W2 + b2
    gemm_mma<false,true,false><<<dim3(Cn/GBN, Mn/GBM), 256, GSMEM>>>(
        ff, wt2, b2, x2, out, Mn, Cn, DFFn);
}

// round 4
// speedup vs baseline: 2.0623x; 1.0855x over previous
#include <cuda_runtime.h>
#include <cstdint>
#include <math.h>

// ---------------- problem constants ----------------
#define Bn   4
#define Tn   2048
#define Cn   1024
#define Hn   16
#define HSn  64
#define DFFn 4096
#define Mn   (Bn*Tn)          // 8192

// ---------------- scratch (__device__ globals; allocation-free) ------------
__device__ float g_buf0[Mn*Cn];                 // ln1 / attn-y / ln2
__device__ float g_qkv [(size_t)Mn*3*Cn];       // merged q|k|v  [M, 3072]
__device__ float g_x2  [Mn*Cn];                 // x + attn
__device__ float g_ff  [(size_t)Mn*DFFn];       // relu(h@W1+b1)
__device__ float g_wtqkv[(size_t)3*Cn*Cn];      // [3072,1024] = (Wq|Wk|Wv)^T
__device__ float g_wto [Cn*Cn];                 // Wo^T  [1024,1024]
__device__ float g_wt1 [(size_t)DFFn*Cn];       // W1^T  [4096,1024]
__device__ float g_wt2 [(size_t)Cn*DFFn];       // W2^T  [1024,4096]
__device__ float g_bqkv[3*Cn];

// ---------------- helpers ----------------
__device__ __forceinline__ uint32_t smem_u32(const void* p) {
    uint32_t a;
    asm("{ .reg .u64 t; cvta.to.shared.u64 t, %1; cvt.u32.u64 %0, t; }" : "=r"(a) : "l"(p));
    return a;
}
__device__ __forceinline__ float rtf32(float x) {
    float r; asm("cvt.rna.tf32.f32 %0, %1;" : "=f"(r) : "f"(x)); return r;
}
__device__ __forceinline__ unsigned long long pk2(float lo, float hi) {
    unsigned long long r; asm("mov.b64 %0, {%1,%2};" : "=l"(r) : "f"(lo), "f"(hi)); return r;
}
__device__ __forceinline__ void upk2(unsigned long long v, float& lo, float& hi) {
    asm("mov.b64 {%0,%1}, %2;" : "=f"(lo), "=f"(hi) : "l"(v));
}
__device__ __forceinline__ unsigned long long fma2(unsigned long long a,
                                                   unsigned long long b,
                                                   unsigned long long c) {
    unsigned long long d;
    asm("fma.rn.f32x2 %0, %1, %2, %3;" : "=l"(d) : "l"(a), "l"(b), "l"(c));
    return d;
}

#define CP16(dst, src) \
    asm volatile("cp.async.cg.shared.global [%0], [%1], 16;" :: "r"(dst), "l"(src))
#define CPCOMMIT() asm volatile("cp.async.commit_group;")
#define CPWAIT1()  asm volatile("cp.async.wait_group 1;" ::: "memory")
#define CPWAIT0()  asm volatile("cp.async.wait_group 0;" ::: "memory")

// mma.sync m16n8k8 tf32 (sm_80 baseline — assembles at compute_103)
__device__ __forceinline__ void mma8(float* d, const uint32_t* a, const uint32_t* b) {
    asm volatile("mma.sync.aligned.m16n8k8.row.col.f32.tf32.tf32.f32 "
        "{%0,%1,%2,%3}, {%4,%5,%6,%7}, {%8,%9}, {%0,%1,%2,%3};"
        : "+f"(d[0]), "+f"(d[1]), "+f"(d[2]), "+f"(d[3])
        : "r"(a[0]), "r"(a[1]), "r"(a[2]), "r"(a[3]), "r"(b[0]), "r"(b[1]));
}

// ---------------- LayerNorm (tf32-rounded out) + optional bias concat ------
// Blocks >= Mn perform the qkv bias concat (12 blocks x 256 = 3072).
__global__ void ln_kernel(const float* __restrict__ x, const float* __restrict__ g,
                          const float* __restrict__ be, float* __restrict__ out,
                          const float* __restrict__ bq, const float* __restrict__ bk,
                          const float* __restrict__ bv, float* __restrict__ bqkv) {
    if (blockIdx.x >= Mn) {
        int t = (blockIdx.x - Mn) * 256 + threadIdx.x;
        bqkv[t] = (t < 1024) ? bq[t] : ((t < 2048) ? bk[t - 1024] : bv[t - 2048]);
        return;
    }
    __shared__ float sh1[8], sh2[8];
    const int row = blockIdx.x;
    const int t = threadIdx.x;
    float4 v = ((const float4*)(x + (size_t)row * Cn))[t];

    float s = v.x + v.y + v.z + v.w;
    #pragma unroll
    for (int o = 16; o; o >>= 1) s += __shfl_down_sync(0xffffffffu, s, o);
    if ((t & 31) == 0) sh1[t >> 5] = s;
    __syncthreads();
    float mu = (sh1[0]+sh1[1]+sh1[2]+sh1[3]+sh1[4]+sh1[5]+sh1[6]+sh1[7]) * (1.0f/Cn);

    float dx = v.x-mu, dy = v.y-mu, dz = v.z-mu, dw = v.w-mu;
    float ss = dx*dx + dy*dy + dz*dz + dw*dw;
    #pragma unroll
    for (int o = 16; o; o >>= 1) ss += __shfl_down_sync(0xffffffffu, ss, o);
    if ((t & 31) == 0) sh2[t >> 5] = ss;
    __syncthreads();
    float rstd = rsqrtf((sh2[0]+sh2[1]+sh2[2]+sh2[3]+sh2[4]+sh2[5]+sh2[6]+sh2[7])*(1.0f/Cn) + 1e-5f);

    float4 gg = ((const float4*)g)[t];
    float4 bb = ((const float4*)be)[t];
    float4 r;
    r.x = rtf32(dx*rstd*gg.x + bb.x);
    r.y = rtf32(dy*rstd*gg.y + bb.y);
    r.z = rtf32(dz*rstd*gg.z + bb.z);
    r.w = rtf32(dw*rstd*gg.w + bb.w);
    ((float4*)(out + (size_t)row * Cn))[t] = r;
}

// ---- transpose up to 3 matrices W[K,N] -> Wt[N,K] (tf32-rounded), z picks --
__global__ void transpose_tf32(const float* __restrict__ Wa, const float* __restrict__ Wb,
                               const float* __restrict__ Wc, float* __restrict__ Wt,
                               int K, int N) {
    const float* W = (blockIdx.z == 0) ? Wa : (blockIdx.z == 1) ? Wb : Wc;
    float* dst = Wt + (size_t)blockIdx.z * N * K;
    __shared__ float t[32][33];
    int n0 = blockIdx.x * 32, k0 = blockIdx.y * 32;
    int tx = threadIdx.x, ty = threadIdx.y;     // 32 x 8
    #pragma unroll
    for (int i = 0; i < 32; i += 8)
        t[ty + i][tx] = W[(size_t)(k0 + ty + i) * N + n0 + tx];
    __syncthreads();
    #pragma unroll
    for (int i = 0; i < 32; i += 8)
        dst[(size_t)(n0 + ty + i) * K + k0 + tx] = rtf32(t[tx][ty + i]);
}

// ---------------- tf32 mma.sync GEMM: C = A[M,K] @ Bt[N,K]^T + bias --------
// block tile 128x128x32, 256 thr = 8 warps (2m x 4n), warp tile 64x32.
// 2-stage cp.async pipeline, 2 CTAs/SM for bubble filling.
#define GBM 128
#define GBN 128
#define GBK 32
#define APAD 36
#define STG (GBM*APAD + GBN*APAD)        // floats per stage (9216)
#define GSMEM (2*STG*4)                  // 73728 bytes

template<bool RELU, bool RES, bool RND>
__global__ __launch_bounds__(256, 2) void gemm_mma(
        const float* __restrict__ A, const float* __restrict__ Bt,
        const float* __restrict__ bias, const float* __restrict__ res,
        float* __restrict__ Cout, int M, int N, int K) {
    extern __shared__ float smf[];
    const int tid = threadIdx.x;
    const int lane = tid & 31;
    const int wid = tid >> 5;
    const int g = lane >> 2, t4 = lane & 3;
    const int wm = wid >> 2, wn = wid & 3;       // 2 x 4 warps
    const int bm = blockIdx.y * GBM;
    const int bn = blockIdx.x * GBN;

    float acc[4][4][4];
    #pragma unroll
    for (int i = 0; i < 4; i++)
        #pragma unroll
        for (int j = 0; j < 4; j++)
            #pragma unroll
            for (int p = 0; p < 4; p++) acc[i][j][p] = 0.0f;

    const uint32_t sm0 = smem_u32(smf);

    auto load_chunk = [&](int c, int s) {
        const uint32_t sA = sm0 + s * (STG * 4);
        const uint32_t sB = sA + GBM * APAD * 4;
        const int kc = c * GBK;
        const int r = tid >> 3, cv = tid & 7;    // 32 rows x 8 float4 per pass
        #pragma unroll
        for (int j = 0; j < 4; j++)
            CP16(sA + (r + j*32) * (APAD*4) + cv*16,
                 A + (size_t)(bm + r + j*32) * K + kc + cv*4);
        #pragma unroll
        for (int j = 0; j < 4; j++)
            CP16(sB + (r + j*32) * (APAD*4) + cv*16,
                 Bt + (size_t)(bn + r + j*32) * K + kc + cv*4);
    };

    load_chunk(0, 0); CPCOMMIT();
    load_chunk(1, 1); CPCOMMIT();

    const int nc = K / GBK;
    for (int c = 0; c < nc; c++) {
        if (c + 1 < nc) { CPWAIT1(); } else { CPWAIT0(); }
        __syncthreads();

        const uint32_t* As = (const uint32_t*)(smf + (c & 1) * STG);
        const uint32_t* Bs = As + GBM * APAD;
        #pragma unroll
        for (int kk = 0; kk < 4; kk++) {
            const int kb = kk * 8;
            uint32_t a[4][4], b[4][2];
            #pragma unroll
            for (int im = 0; im < 4; im++) {
                int r0 = wm*64 + im*16 + g;
                a[im][0] = As[r0*APAD + kb + t4];
                a[im][1] = As[(r0+8)*APAD + kb + t4];
                a[im][2] = As[r0*APAD + kb + t4 + 4];
                a[im][3] = As[(r0+8)*APAD + kb + t4 + 4];
            }
            #pragma unroll
            for (int in = 0; in < 4; in++) {
                int n0 = wn*32 + in*8 + g;
                b[in][0] = Bs[n0*APAD + kb + t4];
                b[in][1] = Bs[n0*APAD + kb + t4 + 4];
            }
            #pragma unroll
            for (int im = 0; im < 4; im++)
                #pragma unroll
                for (int in = 0; in < 4; in++)
                    mma8(acc[im][in], a[im], b[in]);
        }
        __syncthreads();
        if (c + 2 < nc) { load_chunk(c + 2, c & 1); CPCOMMIT(); }
    }

    // ---- epilogue: frags -> global (bias / relu / rnd / residual)
    #pragma unroll
    for (int im = 0; im < 4; im++) {
        #pragma unroll
        for (int in = 0; in < 4; in++) {
            const float* av = acc[im][in];
            int r0 = bm + wm*64 + im*16 + g;
            int c0 = bn + wn*32 + in*8 + t4*2;
            float b0 = bias[c0], b1 = bias[c0 + 1];
            #pragma unroll
            for (int h = 0; h < 2; h++) {
                int row = r0 + h * 8;
                float v0 = av[h*2 + 0] + b0;
                float v1 = av[h*2 + 1] + b1;
                if (RELU) { v0 = fmaxf(v0, 0.f); v1 = fmaxf(v1, 0.f); }
                if (RND)  { v0 = rtf32(v0); v1 = rtf32(v1); }
                if (RES) {
                    const float2 rr = *(const float2*)(res + (size_t)row * N + c0);
                    v0 += rr.x; v1 += rr.y;
                }
                *(float2*)(Cout + (size_t)row * N + c0) = make_float2(v0, v1);
            }
        }
    }
}

// ---------------- fused causal attention (f32x2 packed math) ---------------
__global__ __launch_bounds__(64) void attn_kernel(
        const float* __restrict__ Q, const float* __restrict__ Kg,
        const float* __restrict__ Vg, float* __restrict__ Y, int ldq) {
    __shared__ float Ks[64][68];
    __shared__ float Vs[64][68];
    const int qt = blockIdx.x;
    const int bh = blockIdx.y;
    const int b = bh >> 4, h = bh & 15;
    const int ql = threadIdx.x;
    const int qi = qt * 64 + ql;

    const float* qrow = Q + (size_t)(b * Tn + qi) * ldq + h * HSn;
    unsigned long long q2[32];
    #pragma unroll
    for (int d = 0; d < HSn; d += 4) {
        float4 qv = *(const float4*)(qrow + d);
        q2[d/2]   = pk2(qv.x * 0.125f, qv.y * 0.125f);
        q2[d/2+1] = pk2(qv.z * 0.125f, qv.w * 0.125f);
    }

    float m = -1e30f, l = 0.0f;
    unsigned long long o2[32];
    #pragma unroll
    for (int d = 0; d < 32; d++) o2[d] = 0ull;

    for (int kt = 0; kt <= qt; kt++) {
        #pragma unroll
        for (int i = 0; i < 16; i++) {
            int fid = threadIdx.x + i * 64;
            int r = fid >> 4, dv = (fid & 15) << 2;
            size_t gidx = (size_t)(b * Tn + kt * 64 + r) * ldq + h * HSn + dv;
            *(float4*)&Ks[r][dv] = *(const float4*)(Kg + gidx);
            *(float4*)&Vs[r][dv] = *(const float4*)(Vg + gidx);
        }
        __syncthreads();

        const int kend = (kt == qt) ? (ql + 1) : 64;
        for (int kj = 0; kj < kend; kj++) {
            const unsigned long long* k2 = (const unsigned long long*)&Ks[kj][0];
            unsigned long long sa = 0, sb = 0, sc = 0, sd = 0;
            #pragma unroll
            for (int d = 0; d < 32; d += 4) {
                sa = fma2(q2[d+0], k2[d+0], sa);
                sb = fma2(q2[d+1], k2[d+1], sb);
                sc = fma2(q2[d+2], k2[d+2], sc);
                sd = fma2(q2[d+3], k2[d+3], sd);
            }
            float a0,a1,b0,b1,c0,c1,d0,d1;
            upk2(sa,a0,a1); upk2(sb,b0,b1); upk2(sc,c0,c1); upk2(sd,d0,d1);
            float s = ((a0+a1)+(b0+b1)) + ((c0+c1)+(d0+d1));

            const unsigned long long* v2 = (const unsigned long long*)&Vs[kj][0];
            if (s <= m) {
                float p = __expf(s - m);
                l += p;
                unsigned long long p2 = pk2(p, p);
                #pragma unroll
                for (int d = 0; d < 32; d++) o2[d] = fma2(p2, v2[d], o2[d]);
            } else {
                float corr = __expf(m - s);
                m = s;
                l = fmaf(l, corr, 1.0f);
                unsigned long long c2 = pk2(corr, corr);
                #pragma unroll
                for (int d = 0; d < 32; d++) o2[d] = fma2(c2, o2[d], v2[d]);
            }
        }
        __syncthreads();
    }

    float inv = 1.0f / l;
    float* yrow = Y + (size_t)(b * Tn + qi) * Cn + h * HSn;
    #pragma unroll
    for (int d = 0; d < 32; d += 2) {
        float x0,x1,x2,x3;
        upk2(o2[d], x0, x1); upk2(o2[d+1], x2, x3);
        float4 ov;
        ov.x = rtf32(x0*inv); ov.y = rtf32(x1*inv);
        ov.z = rtf32(x2*inv); ov.w = rtf32(x3*inv);
        *(float4*)(yrow + d*2) = ov;
    }
}

// ---------------- launch ----------------------------------------------------
extern "C" void kernel_launch(void* const* d_in, const int* in_sizes, int n_in,
                              void* d_out, int out_size) {
    const float* x   = (const float*)d_in[0];
    const float* Wq  = (const float*)d_in[1];
    const float* bq  = (const float*)d_in[2];
    const float* Wk  = (const float*)d_in[3];
    const float* bk  = (const float*)d_in[4];
    const float* Wv  = (const float*)d_in[5];
    const float* bv  = (const float*)d_in[6];
    const float* Wo  = (const float*)d_in[7];
    const float* bo  = (const float*)d_in[8];
    const float* W1  = (const float*)d_in[9];
    const float* b1  = (const float*)d_in[10];
    const float* W2  = (const float*)d_in[11];
    const float* b2  = (const float*)d_in[12];
    const float* g1  = (const float*)d_in[13];
    const float* be1 = (const float*)d_in[14];
    const float* g2  = (const float*)d_in[15];
    const float* be2 = (const float*)d_in[16];
    float* out = (float*)d_out;

    float *buf0, *qkv, *x2, *ff, *wtqkv, *wto, *wt1, *wt2, *bqkv;
    cudaGetSymbolAddress((void**)&buf0,  g_buf0);
    cudaGetSymbolAddress((void**)&qkv,   g_qkv);
    cudaGetSymbolAddress((void**)&x2,    g_x2);
    cudaGetSymbolAddress((void**)&ff,    g_ff);
    cudaGetSymbolAddress((void**)&wtqkv, g_wtqkv);
    cudaGetSymbolAddress((void**)&wto,   g_wto);
    cudaGetSymbolAddress((void**)&wt1,   g_wt1);
    cudaGetSymbolAddress((void**)&wt2,   g_wt2);
    cudaGetSymbolAddress((void**)&bqkv,  g_bqkv);

    cudaFuncSetAttribute(gemm_mma<false,false,false>, cudaFuncAttributeMaxDynamicSharedMemorySize, GSMEM);
    cudaFuncSetAttribute(gemm_mma<false,true ,false>, cudaFuncAttributeMaxDynamicSharedMemorySize, GSMEM);
    cudaFuncSetAttribute(gemm_mma<true ,false,true >, cudaFuncAttributeMaxDynamicSharedMemorySize, GSMEM);

    dim3 tb(32, 8);
    // L1: Wq|Wk|Wv -> wtqkv  (z = 3)
    transpose_tf32<<<dim3(Cn/32, Cn/32, 3), tb>>>(Wq, Wk, Wv, wtqkv, Cn, Cn);
    // L2-4: Wo, W1, W2
    transpose_tf32<<<dim3(Cn/32,  Cn/32,  1), tb>>>(Wo, Wo, Wo, wto, Cn,   Cn);
    transpose_tf32<<<dim3(DFFn/32,Cn/32,  1), tb>>>(W1, W1, W1, wt1, Cn,   DFFn);
    transpose_tf32<<<dim3(Cn/32,  DFFn/32,1), tb>>>(W2, W2, W2, wt2, DFFn, Cn);

    // L5: ln1 + qkv bias concat (extra 12 blocks)
    ln_kernel<<<Mn + 12, 256>>>(x, g1, be1, buf0, bq, bk, bv, bqkv);

    // L6: merged qkv = ln1 @ [Wq|Wk|Wv] + b  -> [M, 3072]   (ncu lands here)
    gemm_mma<false,false,false><<<dim3(3*Cn/GBN, Mn/GBM), 256, GSMEM>>>(
        buf0, wtqkv, bqkv, nullptr, qkv, Mn, 3*Cn, Cn);

    // L7: attention -> buf0
    attn_kernel<<<dim3(Tn/64, Bn*Hn), 64>>>(qkv, qkv + Cn, qkv + 2*Cn, buf0, 3*Cn);

    // L8: x2 = x + y @ Wo + bo
    gemm_mma<false,true,false><<<dim3(Cn/GBN, Mn/GBM), 256, GSMEM>>>(
        buf0, wto, bo, x, x2, Mn, Cn, Cn);

    // L9: ln2 -> buf0
    ln_kernel<<<Mn, 256>>>(x2, g2, be2, buf0, nullptr, nullptr, nullptr, nullptr);

    // L10: ff = relu(h @ W1 + b1)  (tf32-rounded)
    gemm_mma<true,false,true><<<dim3(DFFn/GBN, Mn/GBM), 256, GSMEM>>>(
        buf0, wt1, b1, nullptr, ff, Mn, DFFn, Cn);

    // L11: out = x2 + ff @ W2 + b2
    gemm_mma<false,true,false><<<dim3(Cn/GBN, Mn/GBM), 256, GSMEM>>>(
        ff, wt2, b2, x2, out, Mn, Cn, DFFn);
}

// round 6
// speedup vs baseline: 2.0920x; 1.0144x over previous
#include <cuda_runtime.h>
#include <cstdint>
#include <math.h>

// ---------------- problem constants ----------------
#define Bn   4
#define Tn   2048
#define Cn   1024
#define Hn   16
#define HSn  64
#define DFFn 4096
#define Mn   (Bn*Tn)          // 8192

// Data layout contract: every GEMM operand (A rows and Bt rows) is stored
// K-major with each 32-float K-block internally permuted: float that was at
// offset c (0..31) lives at p(c) = (c%4)*8 + c/4.  Inverse: c = (p%8)*4 + p/8.

// ---------------- scratch (__device__ globals; allocation-free) ------------
__device__ float g_buf0[Mn*Cn];                 // ln1 / attn-y / ln2 (PERMUTED)
__device__ float g_qkv [(size_t)Mn*3*Cn];       // merged q|k|v (PLAIN)
__device__ float g_x2  [Mn*Cn];                 // x + attn (PLAIN)
__device__ float g_ff  [(size_t)Mn*DFFn];       // relu(h@W1+b1) (PERMUTED)
__device__ float g_wtqkv[(size_t)3*Cn*Cn];      // (Wq|Wk|Wv)^T (PERMUTED)
__device__ float g_wto [Cn*Cn];                 // Wo^T (PERMUTED)
__device__ float g_wt1 [(size_t)DFFn*Cn];       // W1^T (PERMUTED)
__device__ float g_wt2 [(size_t)Cn*DFFn];       // W2^T (PERMUTED)
__device__ float g_bqkv[3*Cn];

// ---------------- helpers ----------------
__device__ __forceinline__ uint32_t smem_u32(const void* p) {
    uint32_t a;
    asm("{ .reg .u64 t; cvta.to.shared.u64 t, %1; cvt.u32.u64 %0, t; }" : "=r"(a) : "l"(p));
    return a;
}
__device__ __forceinline__ float rtf32(float x) {
    float r; asm("cvt.rna.tf32.f32 %0, %1;" : "=f"(r) : "f"(x)); return r;
}
__device__ __forceinline__ unsigned long long pk2(float lo, float hi) {
    unsigned long long r; asm("mov.b64 %0, {%1,%2};" : "=l"(r) : "f"(lo), "f"(hi)); return r;
}
__device__ __forceinline__ void upk2(unsigned long long v, float& lo, float& hi) {
    asm("mov.b64 {%0,%1}, %2;" : "=f"(lo), "=f"(hi) : "l"(v));
}
__device__ __forceinline__ unsigned long long fma2(unsigned long long a,
                                                   unsigned long long b,
                                                   unsigned long long c) {
    unsigned long long d;
    asm("fma.rn.f32x2 %0, %1, %2, %3;" : "=l"(d) : "l"(a), "l"(b), "l"(c));
    return d;
}

#define CP16(dst, src) \
    asm volatile("cp.async.cg.shared.global [%0], [%1], 16;" :: "r"(dst), "l"(src))
#define CPCOMMIT() asm volatile("cp.async.commit_group;")
#define CPWAIT1()  asm volatile("cp.async.wait_group 1;" ::: "memory")
#define CPWAIT0()  asm volatile("cp.async.wait_group 0;" ::: "memory")

// mma.sync m16n8k8 tf32 (sm_80 baseline)
__device__ __forceinline__ void mma8(float* d, const uint32_t* a, const uint32_t* b) {
    asm volatile("mma.sync.aligned.m16n8k8.row.col.f32.tf32.tf32.f32 "
        "{%0,%1,%2,%3}, {%4,%5,%6,%7}, {%8,%9}, {%0,%1,%2,%3};"
        : "+f"(d[0]), "+f"(d[1]), "+f"(d[2]), "+f"(d[3])
        : "r"(a[0]), "r"(a[1]), "r"(a[2]), "r"(a[3]), "r"(b[0]), "r"(b[1]));
}

// ---------------- LayerNorm (tf32-rounded, PERMUTED out) + bias concat -----
__global__ void ln_kernel(const float* __restrict__ x, const float* __restrict__ g,
                          const float* __restrict__ be, float* __restrict__ out,
                          const float* __restrict__ bq, const float* __restrict__ bk,
                          const float* __restrict__ bv, float* __restrict__ bqkv) {
    if (blockIdx.x >= Mn) {
        int t = (blockIdx.x - Mn) * 256 + threadIdx.x;
        bqkv[t] = (t < 1024) ? bq[t] : ((t < 2048) ? bk[t - 1024] : bv[t - 2048]);
        return;
    }
    __shared__ float sh1[8], sh2[8];
    const int row = blockIdx.x;
    const int t = threadIdx.x;
    float4 v = ((const float4*)(x + (size_t)row * Cn))[t];

    float s = v.x + v.y + v.z + v.w;
    #pragma unroll
    for (int o = 16; o; o >>= 1) s += __shfl_down_sync(0xffffffffu, s, o);
    if ((t & 31) == 0) sh1[t >> 5] = s;
    __syncthreads();
    float mu = (sh1[0]+sh1[1]+sh1[2]+sh1[3]+sh1[4]+sh1[5]+sh1[6]+sh1[7]) * (1.0f/Cn);

    float dx = v.x-mu, dy = v.y-mu, dz = v.z-mu, dw = v.w-mu;
    float ss = dx*dx + dy*dy + dz*dz + dw*dw;
    #pragma unroll
    for (int o = 16; o; o >>= 1) ss += __shfl_down_sync(0xffffffffu, ss, o);
    if ((t & 31) == 0) sh2[t >> 5] = ss;
    __syncthreads();
    float rstd = rsqrtf((sh2[0]+sh2[1]+sh2[2]+sh2[3]+sh2[4]+sh2[5]+sh2[6]+sh2[7])*(1.0f/Cn) + 1e-5f);

    float4 gg = ((const float4*)g)[t];
    float4 bb = ((const float4*)be)[t];
    // cols 4t..4t+3 live in 32-block t>>3 at p = i*8 + (t&7)
    float* orow = out + (size_t)row * Cn + (t >> 3) * 32 + (t & 7);
    orow[0]  = rtf32(dx*rstd*gg.x + bb.x);
    orow[8]  = rtf32(dy*rstd*gg.y + bb.y);
    orow[16] = rtf32(dz*rstd*gg.z + bb.z);
    orow[24] = rtf32(dw*rstd*gg.w + bb.w);
}

// ---- ONE kernel: all weight transposes, PERMUTED K-blocks, tf32-rounded ---
__global__ void transpose_all(const float* __restrict__ Wq, const float* __restrict__ Wk,
                              const float* __restrict__ Wv, const float* __restrict__ Wo,
                              const float* __restrict__ W1, const float* __restrict__ W2,
                              float* __restrict__ wtqkv, float* __restrict__ wto,
                              float* __restrict__ wt1, float* __restrict__ wt2) {
    int idx = blockIdx.x;
    const float* W; float* dst; int K, N, t;
    if (idx < 3072)      { t = idx & 1023; int w = idx >> 10;
                           W = (w==0)?Wq:(w==1)?Wk:Wv; dst = wtqkv + (size_t)w*Cn*Cn;
                           K = Cn; N = Cn; }
    else if (idx < 4096) { t = idx - 3072; W = Wo; dst = wto;  K = Cn;   N = Cn; }
    else if (idx < 8192) { t = idx - 4096; W = W1; dst = wt1;  K = Cn;   N = DFFn; }
    else                 { t = idx - 8192; W = W2; dst = wt2;  K = DFFn; N = Cn; }
    int ntiles = N / 32;
    int n0 = (t % ntiles) * 32, k0 = (t / ntiles) * 32;

    __shared__ float tt[32][33];
    int tx = threadIdx.x, ty = threadIdx.y;     // 32 x 8
    #pragma unroll
    for (int i = 0; i < 32; i += 8)
        tt[ty + i][tx] = W[(size_t)(k0 + ty + i) * N + n0 + tx];
    __syncthreads();
    int pk = (tx & 3) * 8 + (tx >> 2);          // permuted k offset
    #pragma unroll
    for (int i = 0; i < 32; i += 8)
        dst[(size_t)(n0 + ty + i) * K + k0 + pk] = rtf32(tt[tx][ty + i]);
}

// ---------------- tf32 mma.sync GEMM on permuted operands ------------------
// block tile 128x128x32, 256 thr = 8 warps (2m x 4n), 2 stages, 2 CTAs/SM.
// smem: per stage A 16KB + B 16KB (rows = 32 floats, XOR-swizzled 16B units)
#define GBM 128
#define GBN 128
#define GSMEM 65536

template<bool RELU, bool RES, bool RND, bool PERM>
__global__ __launch_bounds__(256, 2) void gemm_mma(
        const float* __restrict__ A, const float* __restrict__ Bt,
        const float* __restrict__ bias, const float* __restrict__ res,
        float* __restrict__ Cout, int M, int N, int K) {
    extern __shared__ float smf[];
    const int tid = threadIdx.x;
    const int lane = tid & 31;
    const int wid = tid >> 5;
    const int g = lane >> 2, t4 = lane & 3;
    const int wm = wid >> 2, wn = wid & 3;       // 2 x 4 warps
    const int bm = blockIdx.y * GBM;
    const int bn = blockIdx.x * GBN;

    float acc[4][4][4];
    #pragma unroll
    for (int i = 0; i < 4; i++)
        #pragma unroll
        for (int j = 0; j < 4; j++)
            #pragma unroll
            for (int p = 0; p < 4; p++) acc[i][j][p] = 0.0f;

    const uint32_t sm0 = smem_u32(smf);

    // stage s at floats 8192*s; A rows 0..127 (32 f each), B at +4096 floats
    auto load_chunk = [&](int c, int s) {
        const uint32_t sA = sm0 + s * 32768;
        const uint32_t sB = sA + 16384;
        const int kc = c * 32;
        const int r = tid >> 3, u = tid & 7;     // base row 0..31, unit 0..7
        const uint32_t du = (u ^ (r & 7)) * 16;  // (r+32j) & 7 == r & 7
        #pragma unroll
        for (int j = 0; j < 4; j++) {
            int rr = r + j * 32;
            CP16(sA + rr * 128 + du, A  + (size_t)(bm + rr) * K + kc + u * 4);
        }
        #pragma unroll
        for (int j = 0; j < 4; j++) {
            int rr = r + j * 32;
            CP16(sB + rr * 128 + du, Bt + (size_t)(bn + rr) * K + kc + u * 4);
        }
    };

    load_chunk(0, 0); CPCOMMIT();
    load_chunk(1, 1); CPCOMMIT();

    const int nc = K / 32;
    for (int c = 0; c < nc; c++) {
        if (c + 1 < nc) { CPWAIT1(); } else { CPWAIT0(); }
        __syncthreads();

        const float* stA = smf + (c & 1) * 8192;
        const float* stB = stA + 4096;
        #pragma unroll
        for (int s = 0; s < 2; s++) {
            float4 av[4][2];
            float4 bv[4];
            #pragma unroll
            for (int im = 0; im < 4; im++) {
                int r = wm*64 + im*16 + g;
                const float* pa = stA + r*32 + (((2*t4 + s) ^ g) << 2);
                av[im][0] = *(const float4*)pa;
                av[im][1] = *(const float4*)(pa + 256);   // row r+8
            }
            #pragma unroll
            for (int in_ = 0; in_ < 4; in_++) {
                int n0 = wn*32 + in_*8 + g;
                const float* pb = stB + n0*32 + (((2*t4 + s) ^ g) << 2);
                bv[in_] = *(const float4*)pb;
            }
            #pragma unroll
            for (int h = 0; h < 2; h++) {
                uint32_t bb[4][2];
                #pragma unroll
                for (int in_ = 0; in_ < 4; in_++) {
                    bb[in_][0] = __float_as_uint(h ? bv[in_].z : bv[in_].x);
                    bb[in_][1] = __float_as_uint(h ? bv[in_].w : bv[in_].y);
                }
                #pragma unroll
                for (int im = 0; im < 4; im++) {
                    uint32_t a[4];
                    a[0] = __float_as_uint(h ? av[im][0].z : av[im][0].x);
                    a[1] = __float_as_uint(h ? av[im][1].z : av[im][1].x);
                    a[2] = __float_as_uint(h ? av[im][0].w : av[im][0].y);
                    a[3] = __float_as_uint(h ? av[im][1].w : av[im][1].y);
                    #pragma unroll
                    for (int in_ = 0; in_ < 4; in_++)
                        mma8(acc[im][in_], a, bb[in_]);
                }
            }
        }
        __syncthreads();
        if (c + 2 < nc) { load_chunk(c + 2, c & 1); CPCOMMIT(); }
    }

    // ---- epilogue
    #pragma unroll
    for (int im = 0; im < 4; im++) {
        #pragma unroll
        for (int in_ = 0; in_ < 4; in_++) {
            const float* av = acc[im][in_];
            int r0 = bm + wm*64 + im*16 + g;
            int c0 = bn + wn*32 + in_*8 + t4*2;
            float b0 = bias[c0], b1 = bias[c0 + 1];
            #pragma unroll
            for (int h = 0; h < 2; h++) {
                int row = r0 + h * 8;
                float v0 = av[h*2 + 0] + b0;
                float v1 = av[h*2 + 1] + b1;
                if (RELU) { v0 = fmaxf(v0, 0.f); v1 = fmaxf(v1, 0.f); }
                if (RND)  { v0 = rtf32(v0); v1 = rtf32(v1); }
                if (RES) {
                    const float2 rr = *(const float2*)(res + (size_t)row * N + c0);
                    v0 += rr.x; v1 += rr.y;
                }
                if (PERM) {
                    int o = in_*8 + t4*2;                 // within 32-block
                    int p0 = (o & 3)*8 + (o >> 2);
                    float* dr = Cout + (size_t)row * N + bn + wn*32;
                    dr[p0] = v0; dr[p0 + 8] = v1;
                } else {
                    *(float2*)(Cout + (size_t)row * N + c0) = make_float2(v0, v1);
                }
            }
        }
    }
}

// ---------------- fused causal attention (f32x2, 16B smem loads) -----------
// Output written PERMUTED (feeds Wo GEMM).
__global__ __launch_bounds__(64) void attn_kernel(
        const float* __restrict__ Q, const float* __restrict__ Kg,
        const float* __restrict__ Vg, float* __restrict__ Y, int ldq) {
    __shared__ __align__(16) float Ks[64][68];
    __shared__ __align__(16) float Vs[64][68];
    const int qt = blockIdx.x;
    const int bh = blockIdx.y;
    const int b = bh >> 4, h = bh & 15;
    const int ql = threadIdx.x;
    const int qi = qt * 64 + ql;

    const float* qrow = Q + (size_t)(b * Tn + qi) * ldq + h * HSn;
    unsigned long long q2[32];
    #pragma unroll
    for (int d = 0; d < HSn; d += 4) {
        float4 qv = *(const float4*)(qrow + d);
        q2[d/2]   = pk2(qv.x * 0.125f, qv.y * 0.125f);
        q2[d/2+1] = pk2(qv.z * 0.125f, qv.w * 0.125f);
    }

    float m = -1e30f, l = 0.0f;
    unsigned long long o2[32];
    #pragma unroll
    for (int d = 0; d < 32; d++) o2[d] = 0ull;

    for (int kt = 0; kt <= qt; kt++) {
        #pragma unroll
        for (int i = 0; i < 16; i++) {
            int fid = threadIdx.x + i * 64;
            int r = fid >> 4, dv = (fid & 15) << 2;
            size_t gidx = (size_t)(b * Tn + kt * 64 + r) * ldq + h * HSn + dv;
            *(float4*)&Ks[r][dv] = *(const float4*)(Kg + gidx);
            *(float4*)&Vs[r][dv] = *(const float4*)(Vg + gidx);
        }
        __syncthreads();

        const int kend = (kt == qt) ? (ql + 1) : 64;
        for (int kj = 0; kj < kend; kj++) {
            const ulonglong2* k4 = (const ulonglong2*)&Ks[kj][0];
            unsigned long long sa = 0, sb = 0, sc = 0, sd = 0;
            #pragma unroll
            for (int i = 0; i < 16; i += 2) {
                ulonglong2 ka = k4[i], kb = k4[i+1];
                sa = fma2(q2[2*i + 0], ka.x, sa);
                sb = fma2(q2[2*i + 1], ka.y, sb);
                sc = fma2(q2[2*i + 2], kb.x, sc);
                sd = fma2(q2[2*i + 3], kb.y, sd);
            }
            float a0,a1,b0,b1,c0,c1,d0,d1;
            upk2(sa,a0,a1); upk2(sb,b0,b1); upk2(sc,c0,c1); upk2(sd,d0,d1);
            float s = ((a0+a1)+(b0+b1)) + ((c0+c1)+(d0+d1));

            const ulonglong2* v4 = (const ulonglong2*)&Vs[kj][0];
            if (s <= m) {
                float p = __expf(s - m);
                l += p;
                unsigned long long p2 = pk2(p, p);
                #pragma unroll
                for (int i = 0; i < 16; i++) {
                    ulonglong2 vv = v4[i];
                    o2[2*i + 0] = fma2(p2, vv.x, o2[2*i + 0]);
                    o2[2*i + 1] = fma2(p2, vv.y, o2[2*i + 1]);
                }
            } else {
                float corr = __expf(m - s);
                m = s;
                l = fmaf(l, corr, 1.0f);
                unsigned long long c2 = pk2(corr, corr);
                #pragma unroll
                for (int i = 0; i < 16; i++) {
                    ulonglong2 vv = v4[i];
                    o2[2*i + 0] = fma2(c2, o2[2*i + 0], vv.x);
                    o2[2*i + 1] = fma2(c2, o2[2*i + 1], vv.y);
                }
            }
        }
        __syncthreads();
    }

    float inv = 1.0f / l;
    float* yrow = Y + (size_t)(b * Tn + qi) * Cn;
    #pragma unroll
    for (int j = 0; j < 16; j++) {               // cols h*64 + 4j.. permuted
        float x0,x1,x2,x3;
        upk2(o2[2*j], x0, x1); upk2(o2[2*j+1], x2, x3);
        float* dr = yrow + h*64 + (j >> 3)*32 + (j & 7);
        dr[0]  = rtf32(x0*inv);
        dr[8]  = rtf32(x1*inv);
        dr[16] = rtf32(x2*inv);
        dr[24] = rtf32(x3*inv);
    }
}

// ---------------- launch ----------------------------------------------------
extern "C" void kernel_launch(void* const* d_in, const int* in_sizes, int n_in,
                              void* d_out, int out_size) {
    const float* x   = (const float*)d_in[0];
    const float* Wq  = (const float*)d_in[1];
    const float* bq  = (const float*)d_in[2];
    const float* Wk  = (const float*)d_in[3];
    const float* bk  = (const float*)d_in[4];
    const float* Wv  = (const float*)d_in[5];
    const float* bv  = (const float*)d_in[6];
    const float* Wo  = (const float*)d_in[7];
    const float* bo  = (const float*)d_in[8];
    const float* W1  = (const float*)d_in[9];
    const float* b1  = (const float*)d_in[10];
    const float* W2  = (const float*)d_in[11];
    const float* b2  = (const float*)d_in[12];
    const float* g1  = (const float*)d_in[13];
    const float* be1 = (const float*)d_in[14];
    const float* g2  = (const float*)d_in[15];
    const float* be2 = (const float*)d_in[16];
    float* out = (float*)d_out;

    float *buf0, *qkv, *x2, *ff, *wtqkv, *wto, *wt1, *wt2, *bqkv;
    cudaGetSymbolAddress((void**)&buf0,  g_buf0);
    cudaGetSymbolAddress((void**)&qkv,   g_qkv);
    cudaGetSymbolAddress((void**)&x2,    g_x2);
    cudaGetSymbolAddress((void**)&ff,    g_ff);
    cudaGetSymbolAddress((void**)&wtqkv, g_wtqkv);
    cudaGetSymbolAddress((void**)&wto,   g_wto);
    cudaGetSymbolAddress((void**)&wt1,   g_wt1);
    cudaGetSymbolAddress((void**)&wt2,   g_wt2);
    cudaGetSymbolAddress((void**)&bqkv,  g_bqkv);

    cudaFuncSetAttribute(gemm_mma<false,false,false,false>, cudaFuncAttributeMaxDynamicSharedMemorySize, GSMEM);
    cudaFuncSetAttribute(gemm_mma<false,true ,false,false>, cudaFuncAttributeMaxDynamicSharedMemorySize, GSMEM);
    cudaFuncSetAttribute(gemm_mma<true ,false,true ,true >, cudaFuncAttributeMaxDynamicSharedMemorySize, GSMEM);

    // L1: all weight transposes (permuted, tf32-rounded)
    transpose_all<<<12288, dim3(32, 8)>>>(Wq, Wk, Wv, Wo, W1, W2,
                                          wtqkv, wto, wt1, wt2);
    // L2: ln1 (permuted out) + qkv bias concat
    ln_kernel<<<Mn + 12, 256>>>(x, g1, be1, buf0, bq, bk, bv, bqkv);

    // L3: merged qkv = ln1 @ [Wq|Wk|Wv] + b  -> plain [M, 3072]
    gemm_mma<false,false,false,false><<<dim3(3*Cn/GBN, Mn/GBM), 256, GSMEM>>>(
        buf0, wtqkv, bqkv, nullptr, qkv, Mn, 3*Cn, Cn);

    // L4: attention -> buf0 (permuted)
    attn_kernel<<<dim3(Tn/64, Bn*Hn), 64>>>(qkv, qkv + Cn, qkv + 2*Cn, buf0, 3*Cn);

    // L5: x2 = x + y @ Wo + bo   (plain out)
    gemm_mma<false,true,false,false><<<dim3(Cn/GBN, Mn/GBM), 256, GSMEM>>>(
        buf0, wto, bo, x, x2, Mn, Cn, Cn);

    // L6: ln2 -> buf0 (permuted)
    ln_kernel<<<Mn, 256>>>(x2, g2, be2, buf0, nullptr, nullptr, nullptr, nullptr);

    // L7: ff = relu(h @ W1 + b1)  (tf32-rounded, permuted out)
    gemm_mma<true,false,true,true><<<dim3(DFFn/GBN, Mn/GBM), 256, GSMEM>>>(
        buf0, wt1, b1, nullptr, ff, Mn, DFFn, Cn);

    // L8: out = x2 + ff @ W2 + b2  (plain out)
    gemm_mma<false,true,false,false><<<dim3(Cn/GBN, Mn/GBM), 256, GSMEM>>>(
        ff, wt2, b2, x2, out, Mn, Cn, DFFn);
}

// round 7
// speedup vs baseline: 2.3622x; 1.1291x over previous
#include <cuda_runtime.h>
#include <cuda_fp16.h>
#include <cstdint>
#include <math.h>

// ---------------- problem constants ----------------
#define Bn   4
#define Tn   2048
#define Cn   1024
#define Hn   16
#define HSn  64
#define DFFn 4096
#define Mn   (Bn*Tn)          // 8192

// Layout contract: every GEMM operand is __half, K-major, with each 64-half
// K-chunk internally permuted. 16B unit lu = 2*t4 + kp (t4=0..3, kp=0..1)
// holds, for mma thread-column t4 and k-step pair kp, the halfs
//   [sp=0: k=32kp+{2t4,2t4+1,2t4+8,2t4+9}] [sp=1: same +16]
// p64(c) maps logical k-offset c (0..63) to its permuted position.

// ---------------- scratch (__device__ globals; allocation-free) ------------
__device__ __half g_buf0[(size_t)Mn*Cn];        // ln1 / attn-y / ln2 (half, permuted)
__device__ float  g_qkv [(size_t)Mn*3*Cn];      // merged q|k|v (fp32, plain)
__device__ float  g_x2  [(size_t)Mn*Cn];        // x + attn (fp32, plain)
__device__ __half g_ff  [(size_t)Mn*DFFn];      // relu(h@W1+b1) (half, permuted)
__device__ __half g_wtqkv[(size_t)3*Cn*Cn];     // (Wq|Wk|Wv)^T (half, permuted)
__device__ __half g_wto [(size_t)Cn*Cn];        // Wo^T
__device__ __half g_wt1 [(size_t)DFFn*Cn];      // W1^T
__device__ __half g_wt2 [(size_t)Cn*DFFn];      // W2^T
__device__ float  g_bqkv[3*Cn];

// ---------------- helpers ----------------
__device__ __forceinline__ uint32_t smem_u32(const void* p) {
    uint32_t a;
    asm("{ .reg .u64 t; cvta.to.shared.u64 t, %1; cvt.u32.u64 %0, t; }" : "=r"(a) : "l"(p));
    return a;
}
__device__ __forceinline__ int p64(int c) {
    int ks = c >> 4, cc = c & 15;
    int kp = ks >> 1, sp = ks & 1;
    int t4 = (cc >> 1) & 3, hi = (cc >> 3) & 1, j = c & 1;
    return (2*t4 + kp)*8 + sp*4 + hi*2 + j;
}
__device__ __forceinline__ unsigned long long pk2(float lo, float hi) {
    unsigned long long r; asm("mov.b64 %0, {%1,%2};" : "=l"(r) : "f"(lo), "f"(hi)); return r;
}
__device__ __forceinline__ void upk2(unsigned long long v, float& lo, float& hi) {
    asm("mov.b64 {%0,%1}, %2;" : "=f"(lo), "=f"(hi) : "l"(v));
}
__device__ __forceinline__ unsigned long long fma2(unsigned long long a,
                                                   unsigned long long b,
                                                   unsigned long long c) {
    unsigned long long d;
    asm("fma.rn.f32x2 %0, %1, %2, %3;" : "=l"(d) : "l"(a), "l"(b), "l"(c));
    return d;
}

#define CP16(dst, src) \
    asm volatile("cp.async.cg.shared.global [%0], [%1], 16;" :: "r"(dst), "l"(src))
#define CPCOMMIT() asm volatile("cp.async.commit_group;")
#define CPWAIT1()  asm volatile("cp.async.wait_group 1;" ::: "memory")
#define CPWAIT0()  asm volatile("cp.async.wait_group 0;" ::: "memory")

// mma.sync m16n8k16 fp16 -> fp32 acc (sm_80 baseline)
__device__ __forceinline__ void mma16(float* d, uint32_t a0, uint32_t a1,
                                      uint32_t a2, uint32_t a3,
                                      uint32_t b0, uint32_t b1) {
    asm volatile("mma.sync.aligned.m16n8k16.row.col.f32.f16.f16.f32 "
        "{%0,%1,%2,%3}, {%4,%5,%6,%7}, {%8,%9}, {%0,%1,%2,%3};"
        : "+f"(d[0]), "+f"(d[1]), "+f"(d[2]), "+f"(d[3])
        : "r"(a0), "r"(a1), "r"(a2), "r"(a3), "r"(b0), "r"(b1));
}

// ---------------- LayerNorm -> half permuted + bias concat -----------------
__global__ void ln_kernel(const float* __restrict__ x, const float* __restrict__ g,
                          const float* __restrict__ be, __half* __restrict__ out,
                          const float* __restrict__ bq, const float* __restrict__ bk,
                          const float* __restrict__ bv, float* __restrict__ bqkv) {
    if (blockIdx.x >= Mn) {
        int t = (blockIdx.x - Mn) * 256 + threadIdx.x;
        bqkv[t] = (t < 1024) ? bq[t] : ((t < 2048) ? bk[t - 1024] : bv[t - 2048]);
        return;
    }
    __shared__ float sh1[8], sh2[8];
    const int row = blockIdx.x;
    const int t = threadIdx.x;
    float4 v = ((const float4*)(x + (size_t)row * Cn))[t];

    float s = v.x + v.y + v.z + v.w;
    #pragma unroll
    for (int o = 16; o; o >>= 1) s += __shfl_down_sync(0xffffffffu, s, o);
    if ((t & 31) == 0) sh1[t >> 5] = s;
    __syncthreads();
    float mu = (sh1[0]+sh1[1]+sh1[2]+sh1[3]+sh1[4]+sh1[5]+sh1[6]+sh1[7]) * (1.0f/Cn);

    float dx = v.x-mu, dy = v.y-mu, dz = v.z-mu, dw = v.w-mu;
    float ss = dx*dx + dy*dy + dz*dz + dw*dw;
    #pragma unroll
    for (int o = 16; o; o >>= 1) ss += __shfl_down_sync(0xffffffffu, ss, o);
    if ((t & 31) == 0) sh2[t >> 5] = ss;
    __syncthreads();
    float rstd = rsqrtf((sh2[0]+sh2[1]+sh2[2]+sh2[3]+sh2[4]+sh2[5]+sh2[6]+sh2[7])*(1.0f/Cn) + 1e-5f);

    float4 gg = ((const float4*)g)[t];
    float4 bb = ((const float4*)be)[t];
    float r0 = dx*rstd*gg.x + bb.x;
    float r1 = dy*rstd*gg.y + bb.y;
    float r2 = dz*rstd*gg.z + bb.z;
    float r3 = dw*rstd*gg.w + bb.w;
    __half* orow = out + (size_t)row * Cn + (t >> 4) * 64;
    int ca = (4 * t) & 63;
    *(__half2*)(orow + p64(ca))     = __floats2half2_rn(r0, r1);
    *(__half2*)(orow + p64(ca + 2)) = __floats2half2_rn(r2, r3);
}

// ---- all weight transposes: W[K,N] -> Wt[N,K] half, permuted --------------
__global__ void transpose_all(const float* __restrict__ Wq, const float* __restrict__ Wk,
                              const float* __restrict__ Wv, const float* __restrict__ Wo,
                              const float* __restrict__ W1, const float* __restrict__ W2,
                              __half* __restrict__ wtqkv, __half* __restrict__ wto,
                              __half* __restrict__ wt1, __half* __restrict__ wt2) {
    int idx = blockIdx.x;
    const float* W; __half* dst; int K, N, t;
    if (idx < 3072)      { t = idx & 1023; int w = idx >> 10;
                           W = (w==0)?Wq:(w==1)?Wk:Wv; dst = wtqkv + (size_t)w*Cn*Cn;
                           K = Cn; N = Cn; }
    else if (idx < 4096) { t = idx - 3072; W = Wo; dst = wto;  K = Cn;   N = Cn; }
    else if (idx < 8192) { t = idx - 4096; W = W1; dst = wt1;  K = Cn;   N = DFFn; }
    else                 { t = idx - 8192; W = W2; dst = wt2;  K = DFFn; N = Cn; }
    int ntiles = N / 32;
    int n0 = (t % ntiles) * 32, k0 = (t / ntiles) * 32;

    __shared__ float tt[32][33];
    int tx = threadIdx.x, ty = threadIdx.y;     // 32 x 8
    #pragma unroll
    for (int i = 0; i < 32; i += 8)
        tt[ty + i][tx] = W[(size_t)(k0 + ty + i) * N + n0 + tx];
    __syncthreads();
    int kk = k0 + tx;
    int kbase = kk & ~63;
    int kperm = kbase + p64(kk & 63);
    #pragma unroll
    for (int i = 0; i < 32; i += 8)
        dst[(size_t)(n0 + ty + i) * K + kperm] = __float2half_rn(tt[tx][ty + i]);
}

// ---------------- fp16 mma GEMM: C = A[M,K] @ Bt[N,K]^T + bias -------------
// block tile 128x128, K-chunks of 64 halfs, 2 stages, 2 CTAs/SM.
#define GBM 128
#define GBN 128
#define GSMEM 65536

template<bool RELU, bool RES, bool PERM>
__global__ __launch_bounds__(256, 2) void gemm_h(
        const __half* __restrict__ A, const __half* __restrict__ Bt,
        const float* __restrict__ bias, const float* __restrict__ res,
        void* __restrict__ CoutV, int M, int N, int K) {
    extern __shared__ __half smh[];
    const int tid = threadIdx.x;
    const int lane = tid & 31;
    const int wid = tid >> 5;
    const int g = lane >> 2, t4 = lane & 3;
    const int wm = wid >> 2, wn = wid & 3;       // 2 x 4 warps
    const int bm = blockIdx.y * GBM;
    const int bn = blockIdx.x * GBN;

    float acc[4][4][4];
    #pragma unroll
    for (int i = 0; i < 4; i++)
        #pragma unroll
        for (int j = 0; j < 4; j++)
            #pragma unroll
            for (int p = 0; p < 4; p++) acc[i][j][p] = 0.0f;

    const uint32_t sm0 = smem_u32(smh);

    // stage s: A tile 128 rows x 128B at sm0+s*32768, B tile at +16384B
    auto load_chunk = [&](int c, int s) {
        const uint32_t sA = sm0 + s * 32768;
        const uint32_t sB = sA + 16384;
        const int kc = c * 64;
        const int r = tid >> 3, u = tid & 7;
        const uint32_t du = (uint32_t)(u ^ (r & 7)) * 16;
        #pragma unroll
        for (int j = 0; j < 4; j++) {
            int rr = r + j * 32;
            CP16(sA + rr * 128 + du, A  + (size_t)(bm + rr) * K + kc + u * 8);
        }
        #pragma unroll
        for (int j = 0; j < 4; j++) {
            int rr = r + j * 32;
            CP16(sB + rr * 128 + du, Bt + (size_t)(bn + rr) * K + kc + u * 8);
        }
    };

    load_chunk(0, 0); CPCOMMIT();
    load_chunk(1, 1); CPCOMMIT();

    const int nc = K >> 6;
    for (int c = 0; c < nc; c++) {
        if (c + 1 < nc) { CPWAIT1(); } else { CPWAIT0(); }
        __syncthreads();

        const __half* stA = smh + (c & 1) * 16384;   // halfs
        const __half* stB = stA + 8192;
        #pragma unroll
        for (int kp = 0; kp < 2; kp++) {
            uint4 Ar[4][2];
            uint4 Br[4];
            #pragma unroll
            for (int im = 0; im < 4; im++) {
                int r = wm*64 + im*16 + g;
                int uoff = ((2*t4 + kp) ^ g) << 3;   // halfs
                Ar[im][0] = *(const uint4*)(stA + r*64 + uoff);
                Ar[im][1] = *(const uint4*)(stA + (r+8)*64 + uoff);
            }
            #pragma unroll
            for (int in_ = 0; in_ < 4; in_++) {
                int n0 = wn*32 + in_*8 + g;
                int uoff = ((2*t4 + kp) ^ g) << 3;
                Br[in_] = *(const uint4*)(stB + n0*64 + uoff);
            }
            #pragma unroll
            for (int sp = 0; sp < 2; sp++) {
                #pragma unroll
                for (int im = 0; im < 4; im++) {
                    uint32_t a0 = sp ? Ar[im][0].z : Ar[im][0].x;
                    uint32_t a1 = sp ? Ar[im][1].z : Ar[im][1].x;
                    uint32_t a2 = sp ? Ar[im][0].w : Ar[im][0].y;
                    uint32_t a3 = sp ? Ar[im][1].w : Ar[im][1].y;
                    #pragma unroll
                    for (int in_ = 0; in_ < 4; in_++) {
                        uint32_t b0 = sp ? Br[in_].z : Br[in_].x;
                        uint32_t b1 = sp ? Br[in_].w : Br[in_].y;
                        mma16(acc[im][in_], a0, a1, a2, a3, b0, b1);
                    }
                }
            }
        }
        __syncthreads();
        if (c + 2 < nc) { load_chunk(c + 2, c & 1); CPCOMMIT(); }
    }

    // ---- epilogue
    #pragma unroll
    for (int im = 0; im < 4; im++) {
        #pragma unroll
        for (int in_ = 0; in_ < 4; in_++) {
            const float* av = acc[im][in_];
            int r0 = bm + wm*64 + im*16 + g;
            int c0 = bn + wn*32 + in_*8 + t4*2;
            float b0 = bias[c0], b1 = bias[c0 + 1];
            #pragma unroll
            for (int h = 0; h < 2; h++) {
                int row = r0 + h * 8;
                float v0 = av[h*2 + 0] + b0;
                float v1 = av[h*2 + 1] + b1;
                if (RELU) { v0 = fmaxf(v0, 0.f); v1 = fmaxf(v1, 0.f); }
                if (RES) {
                    const float2 rr = *(const float2*)(res + (size_t)row * N + c0);
                    v0 += rr.x; v1 += rr.y;
                }
                if (PERM) {
                    int c64 = (wn & 1)*32 + in_*8 + t4*2;
                    __half* dr = (__half*)CoutV + (size_t)row * N + bn + (wn >> 1)*64;
                    *(__half2*)(dr + p64(c64)) = __floats2half2_rn(v0, v1);
                } else {
                    *(float2*)((float*)CoutV + (size_t)row * N + c0) = make_float2(v0, v1);
                }
            }
        }
    }
}

// ---------------- fused causal attention (fp32 math, 128 thr/block) --------
// Reads fp32 q/k/v (plain); writes half permuted (feeds Wo GEMM).
__global__ __launch_bounds__(128) void attn_kernel(
        const float* __restrict__ Q, const float* __restrict__ Kg,
        const float* __restrict__ Vg, __half* __restrict__ Y, int ldq) {
    __shared__ __align__(16) float Ks[64][68];
    __shared__ __align__(16) float Vs[64][68];
    const int qt = blockIdx.x;                   // 128-row q tile
    const int bh = blockIdx.y;
    const int b = bh >> 4, h = bh & 15;
    const int ql = threadIdx.x;                  // 0..127
    const int qi = qt * 128 + ql;

    const float* qrow = Q + (size_t)(b * Tn + qi) * ldq + h * HSn;
    unsigned long long q2[32];
    #pragma unroll
    for (int d = 0; d < HSn; d += 4) {
        float4 qv = *(const float4*)(qrow + d);
        q2[d/2]   = pk2(qv.x * 0.125f, qv.y * 0.125f);
        q2[d/2+1] = pk2(qv.z * 0.125f, qv.w * 0.125f);
    }

    float m = -1e30f, l = 0.0f;
    unsigned long long o2[32];
    #pragma unroll
    for (int d = 0; d < 32; d++) o2[d] = 0ull;

    const int ktmax = 2 * qt + 1;                // last 64-row k tile index
    for (int kt = 0; kt <= ktmax; kt++) {
        #pragma unroll
        for (int i = 0; i < 8; i++) {
            int fid = threadIdx.x + i * 128;
            int r = fid >> 4, dv = (fid & 15) << 2;
            size_t gidx = (size_t)(b * Tn + kt * 64 + r) * ldq + h * HSn + dv;
            *(float4*)&Ks[r][dv] = *(const float4*)(Kg + gidx);
            *(float4*)&Vs[r][dv] = *(const float4*)(Vg + gidx);
        }
        __syncthreads();

        int kend = qi - kt * 64 + 1;
        if (kend > 64) kend = 64;
        for (int kj = 0; kj < kend; kj++) {
            const ulonglong2* k4 = (const ulonglong2*)&Ks[kj][0];
            unsigned long long sa = 0, sb = 0, sc = 0, sd = 0;
            #pragma unroll
            for (int i = 0; i < 16; i += 2) {
                ulonglong2 ka = k4[i], kb = k4[i+1];
                sa = fma2(q2[2*i + 0], ka.x, sa);
                sb = fma2(q2[2*i + 1], ka.y, sb);
                sc = fma2(q2[2*i + 2], kb.x, sc);
                sd = fma2(q2[2*i + 3], kb.y, sd);
            }
            float a0,a1,b0,b1,c0,c1,d0,d1;
            upk2(sa,a0,a1); upk2(sb,b0,b1); upk2(sc,c0,c1); upk2(sd,d0,d1);
            float s = ((a0+a1)+(b0+b1)) + ((c0+c1)+(d0+d1));

            const ulonglong2* v4 = (const ulonglong2*)&Vs[kj][0];
            if (s <= m) {
                float p = __expf(s - m);
                l += p;
                unsigned long long p2 = pk2(p, p);
                #pragma unroll
                for (int i = 0; i < 16; i++) {
                    ulonglong2 vv = v4[i];
                    o2[2*i + 0] = fma2(p2, vv.x, o2[2*i + 0]);
                    o2[2*i + 1] = fma2(p2, vv.y, o2[2*i + 1]);
                }
            } else {
                float corr = __expf(m - s);
                m = s;
                l = fmaf(l, corr, 1.0f);
                unsigned long long c2 = pk2(corr, corr);
                #pragma unroll
                for (int i = 0; i < 16; i++) {
                    ulonglong2 vv = v4[i];
                    o2[2*i + 0] = fma2(c2, o2[2*i + 0], vv.x);
                    o2[2*i + 1] = fma2(c2, o2[2*i + 1], vv.y);
                }
            }
        }
        __syncthreads();
    }

    float inv = 1.0f / l;
    __half* yrow = Y + (size_t)(b * Tn + qi) * Cn + h * 64;
    #pragma unroll
    for (int j = 0; j < 16; j++) {
        float x0,x1,x2,x3;
        upk2(o2[2*j], x0, x1); upk2(o2[2*j+1], x2, x3);
        *(__half2*)(yrow + p64(4*j))     = __floats2half2_rn(x0*inv, x1*inv);
        *(__half2*)(yrow + p64(4*j + 2)) = __floats2half2_rn(x2*inv, x3*inv);
    }
}

// ---------------- launch ----------------------------------------------------
extern "C" void kernel_launch(void* const* d_in, const int* in_sizes, int n_in,
                              void* d_out, int out_size) {
    const float* x   = (const float*)d_in[0];
    const float* Wq  = (const float*)d_in[1];
    const float* bq  = (const float*)d_in[2];
    const float* Wk  = (const float*)d_in[3];
    const float* bk  = (const float*)d_in[4];
    const float* Wv  = (const float*)d_in[5];
    const float* bv  = (const float*)d_in[6];
    const float* Wo  = (const float*)d_in[7];
    const float* bo  = (const float*)d_in[8];
    const float* W1  = (const float*)d_in[9];
    const float* b1  = (const float*)d_in[10];
    const float* W2  = (const float*)d_in[11];
    const float* b2  = (const float*)d_in[12];
    const float* g1  = (const float*)d_in[13];
    const float* be1 = (const float*)d_in[14];
    const float* g2  = (const float*)d_in[15];
    const float* be2 = (const float*)d_in[16];
    float* out = (float*)d_out;

    __half *buf0, *ff, *wtqkv, *wto, *wt1, *wt2;
    float *qkv, *x2, *bqkv;
    cudaGetSymbolAddress((void**)&buf0,  g_buf0);
    cudaGetSymbolAddress((void**)&qkv,   g_qkv);
    cudaGetSymbolAddress((void**)&x2,    g_x2);
    cudaGetSymbolAddress((void**)&ff,    g_ff);
    cudaGetSymbolAddress((void**)&wtqkv, g_wtqkv);
    cudaGetSymbolAddress((void**)&wto,   g_wto);
    cudaGetSymbolAddress((void**)&wt1,   g_wt1);
    cudaGetSymbolAddress((void**)&wt2,   g_wt2);
    cudaGetSymbolAddress((void**)&bqkv,  g_bqkv);

    cudaFuncSetAttribute(gemm_h<false,false,false>, cudaFuncAttributeMaxDynamicSharedMemorySize, GSMEM);
    cudaFuncSetAttribute(gemm_h<false,true ,false>, cudaFuncAttributeMaxDynamicSharedMemorySize, GSMEM);
    cudaFuncSetAttribute(gemm_h<true ,false,true >, cudaFuncAttributeMaxDynamicSharedMemorySize, GSMEM);

    // L1: all weight transposes (half, permuted)
    transpose_all<<<12288, dim3(32, 8)>>>(Wq, Wk, Wv, Wo, W1, W2,
                                          wtqkv, wto, wt1, wt2);
    // L2: ln1 (half permuted) + qkv bias concat
    ln_kernel<<<Mn + 12, 256>>>(x, g1, be1, buf0, bq, bk, bv, bqkv);

    // L3: merged qkv = ln1 @ [Wq|Wk|Wv] + b  -> fp32 plain [M, 3072]
    gemm_h<false,false,false><<<dim3(3*Cn/GBN, Mn/GBM), 256, GSMEM>>>(
        buf0, wtqkv, bqkv, nullptr, qkv, Mn, 3*Cn, Cn);

    // L4: attention -> buf0 (half permuted)
    attn_kernel<<<dim3(Tn/128, Bn*Hn), 128>>>(qkv, qkv + Cn, qkv + 2*Cn, buf0, 3*Cn);

    // L5: x2 = x + y @ Wo + bo   (fp32 plain)
    gemm_h<false,true,false><<<dim3(Cn/GBN, Mn/GBM), 256, GSMEM>>>(
        buf0, wto, bo, x, x2, Mn, Cn, Cn);

    // L6: ln2 -> buf0 (half permuted)
    ln_kernel<<<Mn, 256>>>(x2, g2, be2, buf0, nullptr, nullptr, nullptr, nullptr);

    // L7: ff = relu(h @ W1 + b1)  (half permuted)
    gemm_h<true,false,true><<<dim3(DFFn/GBN, Mn/GBM), 256, GSMEM>>>(
        buf0, wt1, b1, nullptr, ff, Mn, DFFn, Cn);

    // L8: out = x2 + ff @ W2 + b2  (fp32 plain)
    gemm_h<false,true,false><<<dim3(Cn/GBN, Mn/GBM), 256, GSMEM>>>(
        ff, wt2, b2, x2, out, Mn, Cn, DFFn);
}

// round 9
// speedup vs baseline: 6.6562x; 2.8178x over previous
#include <cuda_runtime.h>
#include <cuda_fp16.h>
#include <cstdint>
#include <math.h>

// ---------------- problem constants ----------------
#define Bn   4
#define Tn   2048
#define Cn   1024
#define Hn   16
#define HSn  64
#define DFFn 4096
#define Mn   (Bn*Tn)          // 8192

// GEMM-operand layout: __half, K-major, each 64-half K-chunk p64-permuted.
// p64(c): unit lu=2*t4+kp holds sp=0: k=32kp+{2t4,2t4+1,2t4+8,2t4+9}, sp=1:+16.

// ---------------- scratch (__device__ globals; allocation-free) ------------
__device__ __half g_buf0[(size_t)Mn*Cn];        // ln1 / attn-y / ln2 (half, permuted)
__device__ __half g_qkv [(size_t)Mn*3*Cn];      // merged q|k|v (half, PLAIN)
__device__ float  g_x2  [(size_t)Mn*Cn];        // x + attn (fp32, plain)
__device__ __half g_ff  [(size_t)Mn*DFFn];      // relu(h@W1+b1) (half, permuted)
__device__ __half g_wtqkv[(size_t)3*Cn*Cn];     // (Wq|Wk|Wv)^T (half, permuted)
__device__ __half g_wto [(size_t)Cn*Cn];        // Wo^T
__device__ __half g_wt1 [(size_t)DFFn*Cn];      // W1^T
__device__ __half g_wt2 [(size_t)Cn*DFFn];      // W2^T
__device__ float  g_bqkv[3*Cn];

// ---------------- helpers ----------------
__device__ __forceinline__ uint32_t smem_u32(const void* p) {
    uint32_t a;
    asm("{ .reg .u64 t; cvta.to.shared.u64 t, %1; cvt.u32.u64 %0, t; }" : "=r"(a) : "l"(p));
    return a;
}
__device__ __forceinline__ int p64(int c) {
    int ks = c >> 4, cc = c & 15;
    int kp = ks >> 1, sp = ks & 1;
    int t4 = (cc >> 1) & 3, hi = (cc >> 3) & 1, j = c & 1;
    return (2*t4 + kp)*8 + sp*4 + hi*2 + j;
}

#define CP16(dst, src) \
    asm volatile("cp.async.cg.shared.global [%0], [%1], 16;" :: "r"(dst), "l"(src))
#define CPCOMMIT() asm volatile("cp.async.commit_group;")
#define CPWAIT1()  asm volatile("cp.async.wait_group 1;" ::: "memory")
#define CPWAIT0()  asm volatile("cp.async.wait_group 0;" ::: "memory")

__device__ __forceinline__ void mma16(float* d, uint32_t a0, uint32_t a1,
                                      uint32_t a2, uint32_t a3,
                                      uint32_t b0, uint32_t b1) {
    asm volatile("mma.sync.aligned.m16n8k16.row.col.f32.f16.f16.f32 "
        "{%0,%1,%2,%3}, {%4,%5,%6,%7}, {%8,%9}, {%0,%1,%2,%3};"
        : "+f"(d[0]), "+f"(d[1]), "+f"(d[2]), "+f"(d[3])
        : "r"(a0), "r"(a1), "r"(a2), "r"(a3), "r"(b0), "r"(b1));
}
__device__ __forceinline__ void ldsm4(uint32_t& r0, uint32_t& r1, uint32_t& r2,
                                      uint32_t& r3, uint32_t a) {
    asm volatile("ldmatrix.sync.aligned.m8n8.x4.shared.b16 {%0,%1,%2,%3}, [%4];"
        : "=r"(r0), "=r"(r1), "=r"(r2), "=r"(r3) : "r"(a));
}
__device__ __forceinline__ void ldsm4t(uint32_t& r0, uint32_t& r1, uint32_t& r2,
                                       uint32_t& r3, uint32_t a) {
    asm volatile("ldmatrix.sync.aligned.m8n8.x4.trans.shared.b16 {%0,%1,%2,%3}, [%4];"
        : "=r"(r0), "=r"(r1), "=r"(r2), "=r"(r3) : "r"(a));
}

// ---------------- LayerNorm -> half permuted + bias concat -----------------
__global__ void ln_kernel(const float* __restrict__ x, const float* __restrict__ g,
                          const float* __restrict__ be, __half* __restrict__ out,
                          const float* __restrict__ bq, const float* __restrict__ bk,
                          const float* __restrict__ bv, float* __restrict__ bqkv) {
    if (blockIdx.x >= Mn) {
        int t = (blockIdx.x - Mn) * 256 + threadIdx.x;
        bqkv[t] = (t < 1024) ? bq[t] : ((t < 2048) ? bk[t - 1024] : bv[t - 2048]);
        return;
    }
    __shared__ float sh1[8], sh2[8];
    const int row = blockIdx.x;
    const int t = threadIdx.x;
    float4 v = ((const float4*)(x + (size_t)row * Cn))[t];

    float s = v.x + v.y + v.z + v.w;
    #pragma unroll
    for (int o = 16; o; o >>= 1) s += __shfl_down_sync(0xffffffffu, s, o);
    if ((t & 31) == 0) sh1[t >> 5] = s;
    __syncthreads();
    float mu = (sh1[0]+sh1[1]+sh1[2]+sh1[3]+sh1[4]+sh1[5]+sh1[6]+sh1[7]) * (1.0f/Cn);

    float dx = v.x-mu, dy = v.y-mu, dz = v.z-mu, dw = v.w-mu;
    float ss = dx*dx + dy*dy + dz*dz + dw*dw;
    #pragma unroll
    for (int o = 16; o; o >>= 1) ss += __shfl_down_sync(0xffffffffu, ss, o);
    if ((t & 31) == 0) sh2[t >> 5] = ss;
    __syncthreads();
    float rstd = rsqrtf((sh2[0]+sh2[1]+sh2[2]+sh2[3]+sh2[4]+sh2[5]+sh2[6]+sh2[7])*(1.0f/Cn) + 1e-5f);

    float4 gg = ((const float4*)g)[t];
    float4 bb = ((const float4*)be)[t];
    float r0 = dx*rstd*gg.x + bb.x;
    float r1 = dy*rstd*gg.y + bb.y;
    float r2 = dz*rstd*gg.z + bb.z;
    float r3 = dw*rstd*gg.w + bb.w;
    __half* orow = out + (size_t)row * Cn + (t >> 4) * 64;
    int ca = (4 * t) & 63;
    *(__half2*)(orow + p64(ca))     = __floats2half2_rn(r0, r1);
    *(__half2*)(orow + p64(ca + 2)) = __floats2half2_rn(r2, r3);
}

// ---- all weight transposes: W[K,N] -> Wt[N,K] half, permuted --------------
__global__ void transpose_all(const float* __restrict__ Wq, const float* __restrict__ Wk,
                              const float* __restrict__ Wv, const float* __restrict__ Wo,
                              const float* __restrict__ W1, const float* __restrict__ W2,
                              __half* __restrict__ wtqkv, __half* __restrict__ wto,
                              __half* __restrict__ wt1, __half* __restrict__ wt2) {
    int idx = blockIdx.x;
    const float* W; __half* dst; int K, N, t;
    if (idx < 3072)      { t = idx & 1023; int w = idx >> 10;
                           W = (w==0)?Wq:(w==1)?Wk:Wv; dst = wtqkv + (size_t)w*Cn*Cn;
                           K = Cn; N = Cn; }
    else if (idx < 4096) { t = idx - 3072; W = Wo; dst = wto;  K = Cn;   N = Cn; }
    else if (idx < 8192) { t = idx - 4096; W = W1; dst = wt1;  K = Cn;   N = DFFn; }
    else                 { t = idx - 8192; W = W2; dst = wt2;  K = DFFn; N = Cn; }
    int ntiles = N / 32;
    int n0 = (t % ntiles) * 32, k0 = (t / ntiles) * 32;

    __shared__ float tt[32][33];
    int tx = threadIdx.x, ty = threadIdx.y;     // 32 x 8
    #pragma unroll
    for (int i = 0; i < 32; i += 8)
        tt[ty + i][tx] = W[(size_t)(k0 + ty + i) * N + n0 + tx];
    __syncthreads();
    int kk = k0 + tx;
    int kperm = (kk & ~63) + p64(kk & 63);
    #pragma unroll
    for (int i = 0; i < 32; i += 8)
        dst[(size_t)(n0 + ty + i) * K + kperm] = __float2half_rn(tt[tx][ty + i]);
}

// ---------------- fp16 mma GEMM: C = A[M,K] @ Bt[N,K]^T + bias -------------
// OUTM: 0 = fp32 plain, 1 = half permuted, 2 = half plain
#define GBM 128
#define GBN 128
#define GSMEM 65536

template<bool RELU, bool RES, int OUTM>
__global__ __launch_bounds__(256, 2) void gemm_h(
        const __half* __restrict__ A, const __half* __restrict__ Bt,
        const float* __restrict__ bias, const float* __restrict__ res,
        void* __restrict__ CoutV, int M, int N, int K) {
    extern __shared__ __half smh[];
    const int tid = threadIdx.x;
    const int lane = tid & 31;
    const int wid = tid >> 5;
    const int g = lane >> 2, t4 = lane & 3;
    const int wm = wid >> 2, wn = wid & 3;       // 2 x 4 warps
    const int bm = blockIdx.y * GBM;
    const int bn = blockIdx.x * GBN;

    float acc[4][4][4];
    #pragma unroll
    for (int i = 0; i < 4; i++)
        #pragma unroll
        for (int j = 0; j < 4; j++)
            #pragma unroll
            for (int p = 0; p < 4; p++) acc[i][j][p] = 0.0f;

    const uint32_t sm0 = smem_u32(smh);

    auto load_chunk = [&](int c, int s) {
        const uint32_t sA = sm0 + s * 32768;
        const uint32_t sB = sA + 16384;
        const int kc = c * 64;
        const int r = tid >> 3, u = tid & 7;
        const uint32_t du = (uint32_t)(u ^ (r & 7)) * 16;
        #pragma unroll
        for (int j = 0; j < 4; j++) {
            int rr = r + j * 32;
            CP16(sA + rr * 128 + du, A  + (size_t)(bm + rr) * K + kc + u * 8);
        }
        #pragma unroll
        for (int j = 0; j < 4; j++) {
            int rr = r + j * 32;
            CP16(sB + rr * 128 + du, Bt + (size_t)(bn + rr) * K + kc + u * 8);
        }
    };

    load_chunk(0, 0); CPCOMMIT();
    load_chunk(1, 1); CPCOMMIT();

    const int nc = K >> 6;
    for (int c = 0; c < nc; c++) {
        if (c + 1 < nc) { CPWAIT1(); } else { CPWAIT0(); }
        __syncthreads();

        const __half* stA = smh + (c & 1) * 16384;
        const __half* stB = stA + 8192;
        #pragma unroll
        for (int kp = 0; kp < 2; kp++) {
            uint4 Ar[4][2];
            uint4 Br[4];
            #pragma unroll
            for (int im = 0; im < 4; im++) {
                int r = wm*64 + im*16 + g;
                int uoff = ((2*t4 + kp) ^ g) << 3;
                Ar[im][0] = *(const uint4*)(stA + r*64 + uoff);
                Ar[im][1] = *(const uint4*)(stA + (r+8)*64 + uoff);
            }
            #pragma unroll
            for (int in_ = 0; in_ < 4; in_++) {
                int n0 = wn*32 + in_*8 + g;
                int uoff = ((2*t4 + kp) ^ g) << 3;
                Br[in_] = *(const uint4*)(stB + n0*64 + uoff);
            }
            #pragma unroll
            for (int sp = 0; sp < 2; sp++) {
                #pragma unroll
                for (int im = 0; im < 4; im++) {
                    uint32_t a0 = sp ? Ar[im][0].z : Ar[im][0].x;
                    uint32_t a1 = sp ? Ar[im][1].z : Ar[im][1].x;
                    uint32_t a2 = sp ? Ar[im][0].w : Ar[im][0].y;
                    uint32_t a3 = sp ? Ar[im][1].w : Ar[im][1].y;
                    #pragma unroll
                    for (int in_ = 0; in_ < 4; in_++) {
                        uint32_t b0 = sp ? Br[in_].z : Br[in_].x;
                        uint32_t b1 = sp ? Br[in_].w : Br[in_].y;
                        mma16(acc[im][in_], a0, a1, a2, a3, b0, b1);
                    }
                }
            }
        }
        __syncthreads();
        if (c + 2 < nc) { load_chunk(c + 2, c & 1); CPCOMMIT(); }
    }

    #pragma unroll
    for (int im = 0; im < 4; im++) {
        #pragma unroll
        for (int in_ = 0; in_ < 4; in_++) {
            const float* av = acc[im][in_];
            int r0 = bm + wm*64 + im*16 + g;
            int c0 = bn + wn*32 + in_*8 + t4*2;
            float b0 = bias[c0], b1 = bias[c0 + 1];
            #pragma unroll
            for (int h = 0; h < 2; h++) {
                int row = r0 + h * 8;
                float v0 = av[h*2 + 0] + b0;
                float v1 = av[h*2 + 1] + b1;
                if (RELU) { v0 = fmaxf(v0, 0.f); v1 = fmaxf(v1, 0.f); }
                if (RES) {
                    const float2 rr = *(const float2*)(res + (size_t)row * N + c0);
                    v0 += rr.x; v1 += rr.y;
                }
                if (OUTM == 1) {
                    int c64 = (wn & 1)*32 + in_*8 + t4*2;
                    __half* dr = (__half*)CoutV + (size_t)row * N + bn + (wn >> 1)*64;
                    *(__half2*)(dr + p64(c64)) = __floats2half2_rn(v0, v1);
                } else if (OUTM == 2) {
                    __half* dr = (__half*)CoutV + (size_t)row * N + c0;
                    *(__half2*)dr = __floats2half2_rn(v0, v1);
                } else {
                    *(float2*)((float*)CoutV + (size_t)row * N + c0) = make_float2(v0, v1);
                }
            }
        }
    }
}

// ---------------- tensor-core flash attention -------------------------------
// Block: 4 warps, 64 q rows per (b,h,q-tile). fp16 mma + ldmatrix.
__global__ __launch_bounds__(128, 4) void attn_mma(
        const __half* __restrict__ qkvh, __half* __restrict__ Y) {
    __shared__ __align__(16) __half Qs[64*64];
    __shared__ __align__(16) __half Ks[64*64];
    __shared__ __align__(16) __half Vs[64*64];
    const int qt = blockIdx.x;
    const int bh = blockIdx.y;
    const int b = bh >> 4, h = bh & 15;
    const int tid = threadIdx.x;
    const int lane = tid & 31, w = tid >> 5;
    const int g = lane >> 2, t4 = lane & 3;

    const uint32_t sQ = smem_u32(Qs), sK = smem_u32(Ks), sV = smem_u32(Vs);
    const size_t ldr = 3 * Cn;

    // ---- load Q tile (64 rows x 128B), swizzled
    {
        int r = tid >> 1, u0 = (tid & 1) * 4;
        const __half* src = qkvh + (size_t)(b*Tn + qt*64 + r) * ldr + h*HSn;
        #pragma unroll
        for (int i = 0; i < 4; i++) {
            int u = u0 + i;
            CP16(sQ + r*128 + ((u ^ (r & 7)) << 4), src + u*8);
        }
    }
    CPCOMMIT(); CPWAIT0();
    __syncthreads();

    // ---- Q frags (scaled by 1/8)
    uint32_t qa[4][4];
    {
        int row16 = lane & 15, selq = lane >> 4;
        int qrow = w*16 + row16;
        uint32_t base = sQ + qrow*128;
        int sw = qrow & 7;
        #pragma unroll
        for (int kc = 0; kc < 4; kc++)
            ldsm4(qa[kc][0], qa[kc][1], qa[kc][2], qa[kc][3],
                  base + (((2*kc + selq) ^ sw) << 4));
        __half2 sc = __floats2half2_rn(0.125f, 0.125f);
        #pragma unroll
        for (int kc = 0; kc < 4; kc++)
            #pragma unroll
            for (int i = 0; i < 4; i++) {
                __half2 v = __hmul2(*(__half2*)&qa[kc][i], sc);
                qa[kc][i] = *(uint32_t*)&v;
            }
    }

    float oacc[8][4];
    #pragma unroll
    for (int t = 0; t < 8; t++)
        #pragma unroll
        for (int i = 0; i < 4; i++) oacc[t][i] = 0.0f;
    float m0 = -1e30f, m1 = -1e30f, l0 = 0.0f, l1 = 0.0f;
    const int rw0 = w*16 + g;

    const int sel = lane >> 3, subl = lane & 7;
    const int krow0 = (sel >> 1)*8 + subl;
    const int ksw = krow0 & 7, kub = sel & 1;
    const int vrow0 = (sel & 1)*8 + subl;
    const int vsw = vrow0 & 7, vus = sel >> 1;

    for (int kt = 0; kt <= qt; kt++) {
        __syncthreads();
        {
            int r = tid >> 1, u0 = (tid & 1) * 4;
            const __half* ksrc = qkvh + (size_t)(b*Tn + kt*64 + r) * ldr + Cn + h*HSn;
            const __half* vsrc = ksrc + Cn;
            #pragma unroll
            for (int i = 0; i < 4; i++) {
                int u = u0 + i;
                uint32_t du = (uint32_t)(u ^ (r & 7)) << 4;
                CP16(sK + r*128 + du, ksrc + u*8);
                CP16(sV + r*128 + du, vsrc + u*8);
            }
        }
        CPCOMMIT(); CPWAIT0();
        __syncthreads();

        // ---- S = Q K^T
        float sacc[8][4];
        #pragma unroll
        for (int j = 0; j < 8; j++)
            #pragma unroll
            for (int i = 0; i < 4; i++) sacc[j][i] = 0.0f;
        #pragma unroll
        for (int kc = 0; kc < 4; kc++) {
            #pragma unroll
            for (int jj = 0; jj < 4; jj++) {
                uint32_t b0, b1, b2, b3;
                ldsm4(b0, b1, b2, b3,
                      sK + (16*jj + krow0)*128 + (((2*kc + kub) ^ ksw) << 4));
                mma16(sacc[2*jj],   qa[kc][0], qa[kc][1], qa[kc][2], qa[kc][3], b0, b1);
                mma16(sacc[2*jj+1], qa[kc][0], qa[kc][1], qa[kc][2], qa[kc][3], b2, b3);
            }
        }

        // ---- causal mask on diagonal tile
        if (kt == qt) {
            #pragma unroll
            for (int j = 0; j < 8; j++) {
                int c0 = 8*j + 2*t4;
                if (c0     > rw0)     sacc[j][0] = -1e30f;
                if (c0 + 1 > rw0)     sacc[j][1] = -1e30f;
                if (c0     > rw0 + 8) sacc[j][2] = -1e30f;
                if (c0 + 1 > rw0 + 8) sacc[j][3] = -1e30f;
            }
        }

        // ---- online softmax (m reduced across quad each tile)
        float mx0 = -1e30f, mx1 = -1e30f;
        #pragma unroll
        for (int j = 0; j < 8; j++) {
            mx0 = fmaxf(mx0, fmaxf(sacc[j][0], sacc[j][1]));
            mx1 = fmaxf(mx1, fmaxf(sacc[j][2], sacc[j][3]));
        }
        mx0 = fmaxf(mx0, __shfl_xor_sync(0xffffffffu, mx0, 1));
        mx0 = fmaxf(mx0, __shfl_xor_sync(0xffffffffu, mx0, 2));
        mx1 = fmaxf(mx1, __shfl_xor_sync(0xffffffffu, mx1, 1));
        mx1 = fmaxf(mx1, __shfl_xor_sync(0xffffffffu, mx1, 2));
        float mn0 = fmaxf(m0, mx0), mn1 = fmaxf(m1, mx1);
        float f0 = __expf(m0 - mn0), f1 = __expf(m1 - mn1);
        m0 = mn0; m1 = mn1;
        l0 *= f0; l1 *= f1;
        #pragma unroll
        for (int t = 0; t < 8; t++) {
            oacc[t][0] *= f0; oacc[t][1] *= f0;
            oacc[t][2] *= f1; oacc[t][3] *= f1;
        }

        uint32_t pa[8][2];
        #pragma unroll
        for (int j = 0; j < 8; j++) {
            float p00 = __expf(sacc[j][0] - m0), p01 = __expf(sacc[j][1] - m0);
            float p10 = __expf(sacc[j][2] - m1), p11 = __expf(sacc[j][3] - m1);
            __half2 ha = __floats2half2_rn(p00, p01);
            __half2 hb = __floats2half2_rn(p10, p11);
            float2 fa = __half22float2(ha), fb = __half22float2(hb);
            l0 += fa.x + fa.y; l1 += fb.x + fb.y;
            pa[j][0] = *(uint32_t*)&ha;
            pa[j][1] = *(uint32_t*)&hb;
        }

        // ---- O += P V
        #pragma unroll
        for (int kc = 0; kc < 4; kc++) {
            uint32_t a0 = pa[2*kc][0], a1 = pa[2*kc][1];
            uint32_t a2 = pa[2*kc+1][0], a3 = pa[2*kc+1][1];
            #pragma unroll
            for (int jj = 0; jj < 4; jj++) {
                uint32_t b0, b1, b2, b3;
                ldsm4t(b0, b1, b2, b3,
                       sV + (16*kc + vrow0)*128 + (((2*jj + vus) ^ vsw) << 4));
                mma16(oacc[2*jj],   a0, a1, a2, a3, b0, b1);
                mma16(oacc[2*jj+1], a0, a1, a2, a3, b2, b3);
            }
        }
    }

    // ---- FIX: reduce partial l across the t4 quad (m is already shared)
    l0 += __shfl_xor_sync(0xffffffffu, l0, 1);
    l0 += __shfl_xor_sync(0xffffffffu, l0, 2);
    l1 += __shfl_xor_sync(0xffffffffu, l1, 1);
    l1 += __shfl_xor_sync(0xffffffffu, l1, 2);

    // ---- normalize + write permuted half
    float i0 = 1.0f / l0, i1 = 1.0f / l1;
    const size_t orow0 = (size_t)(b*Tn + qt*64 + rw0) * Cn + h*HSn;
    const size_t orow1 = orow0 + (size_t)8 * Cn;
    #pragma unroll
    for (int t = 0; t < 8; t++) {
        int pp = p64(8*t + 2*t4);
        *(__half2*)(Y + orow0 + pp) = __floats2half2_rn(oacc[t][0]*i0, oacc[t][1]*i0);
        *(__half2*)(Y + orow1 + pp) = __floats2half2_rn(oacc[t][2]*i1, oacc[t][3]*i1);
    }
}

// ---------------- launch ----------------------------------------------------
extern "C" void kernel_launch(void* const* d_in, const int* in_sizes, int n_in,
                              void* d_out, int out_size) {
    const float* x   = (const float*)d_in[0];
    const float* Wq  = (const float*)d_in[1];
    const float* bq  = (const float*)d_in[2];
    const float* Wk  = (const float*)d_in[3];
    const float* bk  = (const float*)d_in[4];
    const float* Wv  = (const float*)d_in[5];
    const float* bv  = (const float*)d_in[6];
    const float* Wo  = (const float*)d_in[7];
    const float* bo  = (const float*)d_in[8];
    const float* W1  = (const float*)d_in[9];
    const float* b1  = (const float*)d_in[10];
    const float* W2  = (const float*)d_in[11];
    const float* b2  = (const float*)d_in[12];
    const float* g1  = (const float*)d_in[13];
    const float* be1 = (const float*)d_in[14];
    const float* g2  = (const float*)d_in[15];
    const float* be2 = (const float*)d_in[16];
    float* out = (float*)d_out;

    __half *buf0, *qkv, *ff, *wtqkv, *wto, *wt1, *wt2;
    float *x2, *bqkv;
    cudaGetSymbolAddress((void**)&buf0,  g_buf0);
    cudaGetSymbolAddress((void**)&qkv,   g_qkv);
    cudaGetSymbolAddress((void**)&x2,    g_x2);
    cudaGetSymbolAddress((void**)&ff,    g_ff);
    cudaGetSymbolAddress((void**)&wtqkv, g_wtqkv);
    cudaGetSymbolAddress((void**)&wto,   g_wto);
    cudaGetSymbolAddress((void**)&wt1,   g_wt1);
    cudaGetSymbolAddress((void**)&wt2,   g_wt2);
    cudaGetSymbolAddress((void**)&bqkv,  g_bqkv);

    cudaFuncSetAttribute(gemm_h<false,false,2>, cudaFuncAttributeMaxDynamicSharedMemorySize, GSMEM);
    cudaFuncSetAttribute(gemm_h<false,true ,0>, cudaFuncAttributeMaxDynamicSharedMemorySize, GSMEM);
    cudaFuncSetAttribute(gemm_h<true ,false,1>, cudaFuncAttributeMaxDynamicSharedMemorySize, GSMEM);

    // L1: weight transposes (half, permuted)
    transpose_all<<<12288, dim3(32, 8)>>>(Wq, Wk, Wv, Wo, W1, W2,
                                          wtqkv, wto, wt1, wt2);
    // L2: ln1 (half permuted) + qkv bias concat
    ln_kernel<<<Mn + 12, 256>>>(x, g1, be1, buf0, bq, bk, bv, bqkv);

    // L3: merged qkv = ln1 @ [Wq|Wk|Wv] + b -> half PLAIN [M, 3072]
    gemm_h<false,false,2><<<dim3(3*Cn/GBN, Mn/GBM), 256, GSMEM>>>(
        buf0, wtqkv, bqkv, nullptr, qkv, Mn, 3*Cn, Cn);

    // L4: tensor-core attention -> buf0 (half permuted)
    attn_mma<<<dim3(Tn/64, Bn*Hn), 128>>>(qkv, buf0);

    // L5: x2 = x + y @ Wo + bo   (fp32 plain)
    gemm_h<false,true,0><<<dim3(Cn/GBN, Mn/GBM), 256, GSMEM>>>(
        buf0, wto, bo, x, x2, Mn, Cn, Cn);

    // L6: ln2 -> buf0 (half permuted)
    ln_kernel<<<Mn, 256>>>(x2, g2, be2, buf0, nullptr, nullptr, nullptr, nullptr);

    // L7: ff = relu(h @ W1 + b1)  (half permuted)
    gemm_h<true,false,1><<<dim3(DFFn/GBN, Mn/GBM), 256, GSMEM>>>(
        buf0, wt1, b1, nullptr, ff, Mn, DFFn, Cn);

    // L8: out = x2 + ff @ W2 + b2  (fp32 plain)
    gemm_h<false,true,0><<<dim3(Cn/GBN, Mn/GBM), 256, GSMEM>>>(
        ff, wt2, b2, x2, out, Mn, Cn, DFFn);
}